// round 1
// baseline (speedup 1.0000x reference)
#include <cuda_runtime.h>
#include <math.h>
#include <stdint.h>

// Problem constants
#define Bc   2
#define Sc   2048
#define Hc   2048
#define NHc  32
#define NKVc 8
#define HDc  64
#define MQ   (Bc * Sc)          // 4096 rows

// ---------------------------------------------------------------------------
// Scratch (device globals: no allocation allowed in kernel_launch)
// ---------------------------------------------------------------------------
__device__ float g_q  [(size_t)Bc * Sc * NHc  * HDc];   // [B,S,NH,64]  row-major [4096,2048]
__device__ float g_k  [(size_t)Bc * Sc * NKVc * HDc];   // [B,S,NKV,64] row-major [4096,512]
__device__ float g_v  [(size_t)Bc * Sc * NKVc * HDc];
__device__ float g_att[(size_t)Bc * Sc * NHc  * HDc];   // attention out, [4096,2048]
__device__ float g_cos[(size_t)Bc * Sc * HDc];          // [B,S,64]
__device__ float g_sin[(size_t)Bc * Sc * HDc];

// ---------------------------------------------------------------------------
// mRoPE cos/sin table
// sections: d%32 < 16 -> grid 0 (t), else grid 1 (h); w section is empty.
// inv_freq[i] = theta^(-i/32), i = d%32
// ---------------------------------------------------------------------------
__global__ void cossin_kernel(const int* __restrict__ pos,
                              float* __restrict__ cosb,
                              float* __restrict__ sinb) {
    int idx = blockIdx.x * blockDim.x + threadIdx.x;
    if (idx >= Bc * Sc * HDc) return;
    int d  = idx & 63;
    int bs = idx >> 6;                   // b*S + s
    int i  = d & 31;
    int sec = (i < 16) ? 0 : 1;
    float p = (float)pos[sec * (Bc * Sc) + bs];
    // log2(1e6)/32 = 0.6228615177913804
    float inv_freq = exp2f(-0.6228615177913804f * (float)i);
    float ang = p * inv_freq;
    float s, c;
    sincosf(ang, &s, &c);
    cosb[idx] = c;
    sinb[idx] = s;
}

// ---------------------------------------------------------------------------
// RoPE: x' = x*cos + rotate_half(x)*sin, in-place over [B,S,nheads,64]
// one thread handles the (d, d+32) pair, d in [0,32)
// ---------------------------------------------------------------------------
__global__ void rope_kernel(float* __restrict__ X,
                            const float* __restrict__ cosb,
                            const float* __restrict__ sinb,
                            int nheads, int total_pairs) {
    int idx = blockIdx.x * blockDim.x + threadIdx.x;
    if (idx >= total_pairs) return;
    int d    = idx & 31;
    int rest = idx >> 5;                 // (b*S+s)*nheads + h
    int bs   = rest / nheads;
    float* p = X + (size_t)rest * HDc;
    const float* cb = cosb + (size_t)bs * HDc;
    const float* sb = sinb + (size_t)bs * HDc;
    float x1 = p[d], x2 = p[d + 32];
    float c1 = cb[d], s1 = sb[d];
    float c2 = cb[d + 32], s2 = sb[d + 32];
    p[d]      = x1 * c1 - x2 * s1;
    p[d + 32] = x2 * c2 + x1 * s2;
}

// ---------------------------------------------------------------------------
// Classic fp32 SGEMM: C[M,N] = A[M,K] @ B[K,N] (+ bias[N])
// BM=BN=128, BK=16, 8x8 microtile, 256 threads
// ---------------------------------------------------------------------------
#define BM 128
#define BN 128
#define BK 16

__global__ __launch_bounds__(256)
void sgemm_kernel(const float* __restrict__ A, const float* __restrict__ B,
                  const float* __restrict__ bias, float* __restrict__ C,
                  int M, int N, int K) {
    __shared__ __align__(16) float As[BK][BM];
    __shared__ __align__(16) float Bs[BK][BN];

    int bx = blockIdx.x;     // N tile
    int by = blockIdx.y;     // M tile
    int tid  = threadIdx.x;  // 0..255
    int tcol = tid & 15;     // 16 thread cols
    int trow = tid >> 4;     // 16 thread rows

    float acc[8][8];
    #pragma unroll
    for (int i = 0; i < 8; i++)
        #pragma unroll
        for (int j = 0; j < 8; j++) acc[i][j] = 0.f;

    const float* Aptr = A + (size_t)by * BM * K;
    const float* Bptr = B + (size_t)bx * BN;

    for (int k0 = 0; k0 < K; k0 += BK) {
        // load A tile (128x16), transpose into As[k][m]
        #pragma unroll
        for (int i = 0; i < 2; i++) {
            int idx = tid + i * 256;           // 0..511 float4s
            int r  = idx >> 2;                 // row 0..127
            int c4 = idx & 3;                  // f4 col 0..3
            float4 v = *(const float4*)(Aptr + (size_t)r * K + k0 + c4 * 4);
            As[c4 * 4 + 0][r] = v.x;
            As[c4 * 4 + 1][r] = v.y;
            As[c4 * 4 + 2][r] = v.z;
            As[c4 * 4 + 3][r] = v.w;
        }
        // load B tile (16x128)
        #pragma unroll
        for (int i = 0; i < 2; i++) {
            int idx = tid + i * 256;           // 0..511 float4s
            int r  = idx >> 5;                 // row 0..15
            int c4 = idx & 31;                 // f4 col 0..31
            *(float4*)(&Bs[r][c4 * 4]) =
                *(const float4*)(Bptr + (size_t)(k0 + r) * N + c4 * 4);
        }
        __syncthreads();

        #pragma unroll
        for (int kk = 0; kk < BK; kk++) {
            float ra[8], rb[8];
            *(float4*)&ra[0] = *(const float4*)&As[kk][trow * 8];
            *(float4*)&ra[4] = *(const float4*)&As[kk][trow * 8 + 4];
            *(float4*)&rb[0] = *(const float4*)&Bs[kk][tcol * 8];
            *(float4*)&rb[4] = *(const float4*)&Bs[kk][tcol * 8 + 4];
            #pragma unroll
            for (int i = 0; i < 8; i++)
                #pragma unroll
                for (int j = 0; j < 8; j++)
                    acc[i][j] = fmaf(ra[i], rb[j], acc[i][j]);
        }
        __syncthreads();
    }

    // epilogue
    #pragma unroll
    for (int i = 0; i < 8; i++) {
        int m = by * BM + trow * 8 + i;
        float* crow = C + (size_t)m * N + bx * BN + tcol * 8;
        #pragma unroll
        for (int jj = 0; jj < 8; jj += 4) {
            int n = bx * BN + tcol * 8 + jj;
            float4 v;
            v.x = acc[i][jj + 0];
            v.y = acc[i][jj + 1];
            v.z = acc[i][jj + 2];
            v.w = acc[i][jj + 3];
            if (bias) {
                v.x += bias[n + 0]; v.y += bias[n + 1];
                v.z += bias[n + 2]; v.w += bias[n + 3];
            }
            *(float4*)(crow + jj) = v;
        }
    }
}

// ---------------------------------------------------------------------------
// Flash-style causal attention (GQA rep=4)
// One thread owns one q row (q[64], o[64] in registers); 32-key K/V smem tiles.
// Softmax in log2 domain: q pre-scaled by (1/8)*log2(e), p = exp2(s - m).
// ---------------------------------------------------------------------------
__device__ __forceinline__ float fast_exp2(float x) {
    float y;
    asm("ex2.approx.ftz.f32 %0, %1;" : "=f"(y) : "f"(x));
    return y;
}

#define AQB 128   // q rows per CTA (== threads)
#define AKB 32    // keys per smem tile

__global__ __launch_bounds__(AQB)
void attn_kernel(const float* __restrict__ Q, const float* __restrict__ Kg,
                 const float* __restrict__ Vg, float* __restrict__ O) {
    // grid: (S/AQB, NH, B)
    int qb = blockIdx.x, h = blockIdx.y, b = blockIdx.z;
    int kh = h >> 2;                     // NH/NKV = 4
    int tid = threadIdx.x;
    int qi = qb * AQB + tid;             // global query index owned by thread

    __shared__ __align__(16) float Ks[AKB][HDc];
    __shared__ __align__(16) float Vs[AKB][HDc];

    // load own q row, pre-scaled by 1/sqrt(64) * log2(e)
    const float SCALE = 0.125f * 1.4426950408889634f;
    float q[HDc];
    {
        const float4* qp = (const float4*)(Q + ((size_t)(b * Sc + qi) * NHc + h) * HDc);
        #pragma unroll
        for (int d4 = 0; d4 < 16; d4++) {
            float4 v = qp[d4];
            q[d4 * 4 + 0] = v.x * SCALE;
            q[d4 * 4 + 1] = v.y * SCALE;
            q[d4 * 4 + 2] = v.z * SCALE;
            q[d4 * 4 + 3] = v.w * SCALE;
        }
    }

    float o[HDc];
    #pragma unroll
    for (int d = 0; d < HDc; d++) o[d] = 0.f;
    float m = -1e30f, l = 0.f;

    int ntiles = ((qb + 1) * AQB) / AKB;   // keys needed by the largest qi in block

    for (int kt = 0; kt < ntiles; kt++) {
        int kbase = kt * AKB;
        __syncthreads();
        // cooperative load of 32 K rows + 32 V rows (each 64 floats)
        #pragma unroll
        for (int i = 0; i < 4; i++) {
            int idx = tid + i * AQB;           // 0..511 float4s
            int r  = idx >> 4;                 // key row 0..31
            int c4 = idx & 15;                 // f4 col 0..15
            size_t roff = ((size_t)(b * Sc + kbase + r) * NKVc + kh) * HDc;
            ((float4*)&Ks[r][0])[c4] = ((const float4*)(Kg + roff))[c4];
            ((float4*)&Vs[r][0])[c4] = ((const float4*)(Vg + roff))[c4];
        }
        __syncthreads();

        #pragma unroll 1
        for (int c = 0; c < AKB; c += 4) {
            float s0 = 0.f, s1 = 0.f, s2 = 0.f, s3 = 0.f;
            const float4* K0 = (const float4*)&Ks[c + 0][0];
            const float4* K1 = (const float4*)&Ks[c + 1][0];
            const float4* K2 = (const float4*)&Ks[c + 2][0];
            const float4* K3 = (const float4*)&Ks[c + 3][0];
            #pragma unroll
            for (int d4 = 0; d4 < 16; d4++) {
                float4 a = K0[d4], e = K1[d4], f = K2[d4], g = K3[d4];
                float q0 = q[d4 * 4 + 0], q1 = q[d4 * 4 + 1];
                float q2 = q[d4 * 4 + 2], q3 = q[d4 * 4 + 3];
                s0 = fmaf(q0, a.x, s0); s0 = fmaf(q1, a.y, s0);
                s0 = fmaf(q2, a.z, s0); s0 = fmaf(q3, a.w, s0);
                s1 = fmaf(q0, e.x, s1); s1 = fmaf(q1, e.y, s1);
                s1 = fmaf(q2, e.z, s1); s1 = fmaf(q3, e.w, s1);
                s2 = fmaf(q0, f.x, s2); s2 = fmaf(q1, f.y, s2);
                s2 = fmaf(q2, f.z, s2); s2 = fmaf(q3, f.w, s2);
                s3 = fmaf(q0, g.x, s3); s3 = fmaf(q1, g.y, s3);
                s3 = fmaf(q2, g.z, s3); s3 = fmaf(q3, g.w, s3);
            }
            int kg = kbase + c;
            s0 = (kg + 0 <= qi) ? s0 : -1e30f;
            s1 = (kg + 1 <= qi) ? s1 : -1e30f;
            s2 = (kg + 2 <= qi) ? s2 : -1e30f;
            s3 = (kg + 3 <= qi) ? s3 : -1e30f;

            float m4 = fmaxf(fmaxf(s0, s1), fmaxf(s2, s3));
            if (m4 > m) {
                float sc = fast_exp2(m - m4);
                l *= sc;
                #pragma unroll
                for (int d = 0; d < HDc; d++) o[d] *= sc;
                m = m4;
            }
            float p0 = fast_exp2(s0 - m);
            float p1 = fast_exp2(s1 - m);
            float p2 = fast_exp2(s2 - m);
            float p3 = fast_exp2(s3 - m);
            l += (p0 + p1) + (p2 + p3);

            const float4* V0 = (const float4*)&Vs[c + 0][0];
            const float4* V1 = (const float4*)&Vs[c + 1][0];
            const float4* V2 = (const float4*)&Vs[c + 2][0];
            const float4* V3 = (const float4*)&Vs[c + 3][0];
            #pragma unroll
            for (int d4 = 0; d4 < 16; d4++) {
                float4 a = V0[d4], e = V1[d4], f = V2[d4], g = V3[d4];
                o[d4*4+0] = fmaf(p0, a.x, fmaf(p1, e.x, fmaf(p2, f.x, fmaf(p3, g.x, o[d4*4+0]))));
                o[d4*4+1] = fmaf(p0, a.y, fmaf(p1, e.y, fmaf(p2, f.y, fmaf(p3, g.y, o[d4*4+1]))));
                o[d4*4+2] = fmaf(p0, a.z, fmaf(p1, e.z, fmaf(p2, f.z, fmaf(p3, g.z, o[d4*4+2]))));
                o[d4*4+3] = fmaf(p0, a.w, fmaf(p1, e.w, fmaf(p2, f.w, fmaf(p3, g.w, o[d4*4+3]))));
            }
        }
    }

    float inv_l = 1.0f / l;
    float4* op = (float4*)(O + ((size_t)(b * Sc + qi) * NHc + h) * HDc);
    #pragma unroll
    for (int d4 = 0; d4 < 16; d4++) {
        float4 v;
        v.x = o[d4 * 4 + 0] * inv_l;
        v.y = o[d4 * 4 + 1] * inv_l;
        v.z = o[d4 * 4 + 2] * inv_l;
        v.w = o[d4 * 4 + 3] * inv_l;
        op[d4] = v;
    }
}

// ---------------------------------------------------------------------------
// launch
// ---------------------------------------------------------------------------
extern "C" void kernel_launch(void* const* d_in, const int* in_sizes, int n_in,
                              void* d_out, int out_size) {
    (void)in_sizes; (void)n_in; (void)out_size;
    const float* x   = (const float*)d_in[0];
    const int*   pos = (const int*)  d_in[1];
    const float* Wq  = (const float*)d_in[2];
    const float* bq  = (const float*)d_in[3];
    const float* Wk  = (const float*)d_in[4];
    const float* bk  = (const float*)d_in[5];
    const float* Wv  = (const float*)d_in[6];
    const float* bv  = (const float*)d_in[7];
    const float* Wo  = (const float*)d_in[8];
    float* out = (float*)d_out;

    float *q, *k, *v, *att, *cs, *sn;
    cudaGetSymbolAddress((void**)&q,   g_q);
    cudaGetSymbolAddress((void**)&k,   g_k);
    cudaGetSymbolAddress((void**)&v,   g_v);
    cudaGetSymbolAddress((void**)&att, g_att);
    cudaGetSymbolAddress((void**)&cs,  g_cos);
    cudaGetSymbolAddress((void**)&sn,  g_sin);

    // 1) rotary tables
    cossin_kernel<<<(Bc * Sc * HDc + 255) / 256, 256>>>(pos, cs, sn);

    // 2) QKV projections
    sgemm_kernel<<<dim3((NHc * HDc) / BN, MQ / BM), 256>>>(x, Wq, bq, q, MQ, NHc * HDc, Hc);
    sgemm_kernel<<<dim3((NKVc * HDc) / BN, MQ / BM), 256>>>(x, Wk, bk, k, MQ, NKVc * HDc, Hc);
    sgemm_kernel<<<dim3((NKVc * HDc) / BN, MQ / BM), 256>>>(x, Wv, bv, v, MQ, NKVc * HDc, Hc);

    // 3) RoPE on q and k
    rope_kernel<<<(Bc * Sc * NHc * 32 + 255) / 256, 256>>>(q, cs, sn, NHc, Bc * Sc * NHc * 32);
    rope_kernel<<<(Bc * Sc * NKVc * 32 + 255) / 256, 256>>>(k, cs, sn, NKVc, Bc * Sc * NKVc * 32);

    // 4) causal GQA attention
    attn_kernel<<<dim3(Sc / AQB, NHc, Bc), AQB>>>(q, k, v, att);

    // 5) output projection
    sgemm_kernel<<<dim3(Hc / BN, MQ / BM), 256>>>(att, Wo, nullptr, out, MQ, Hc, Hc);
}

// round 3
// speedup vs baseline: 1.4136x; 1.4136x over previous
#include <cuda_runtime.h>
#include <math.h>
#include <stdint.h>

// Problem constants
#define Bc   2
#define Sc   2048
#define Hc   2048
#define NHc  32
#define NKVc 8
#define HDc  64
#define MQ   (Bc * Sc)          // 4096 rows

#if defined(__CUDA_ARCH__) && defined(__CUDA_ARCH_FEAT_SM103_ALL)
#define HAS_TCGEN05 1
#else
#define HAS_TCGEN05 0
#endif

// ---------------------------------------------------------------------------
// Scratch (device globals)
// ---------------------------------------------------------------------------
__device__ float g_q  [(size_t)Bc * Sc * NHc  * HDc];
__device__ float g_k  [(size_t)Bc * Sc * NKVc * HDc];
__device__ float g_v  [(size_t)Bc * Sc * NKVc * HDc];
__device__ float g_att[(size_t)Bc * Sc * NHc  * HDc];
__device__ float g_cos[(size_t)Bc * Sc * HDc];
__device__ float g_sin[(size_t)Bc * Sc * HDc];
// transposed + tf32-split weights: [N, K] row-major
__device__ float g_wqh[(size_t)2048 * 2048], g_wql[(size_t)2048 * 2048];
__device__ float g_wkh[(size_t)512  * 2048], g_wkl[(size_t)512  * 2048];
__device__ float g_wvh[(size_t)512  * 2048], g_wvl[(size_t)512  * 2048];
__device__ float g_woh[(size_t)2048 * 2048], g_wol[(size_t)2048 * 2048];

// ---------------------------------------------------------------------------
// small helpers
// ---------------------------------------------------------------------------
__device__ __forceinline__ uint32_t smem_u32(const void* p) {
    uint32_t a;
    asm("{ .reg .u64 t; cvta.to.shared.u64 t, %1; cvt.u32.u64 %0, t; }" : "=r"(a) : "l"(p));
    return a;
}
__device__ __forceinline__ float tf32_rn(float a) {
    uint32_t u;
    asm("cvt.rna.tf32.f32 %0, %1;" : "=r"(u) : "f"(a));
    return __uint_as_float(u);
}

#if HAS_TCGEN05
__device__ __forceinline__ uint64_t mk_desc(uint32_t addr) {
    // SW128, version=1 (Blackwell), SBO=64, LBO=1, start=addr>>4
    return ((uint64_t)2 << 61) | ((uint64_t)1 << 46) | ((uint64_t)64 << 32) |
           ((uint64_t)1 << 16) | ((uint64_t)((addr >> 4) & 0x3FFF));
}
__device__ __forceinline__ void mma_tf32(uint32_t d, uint64_t ad, uint64_t bd,
                                         uint32_t idesc, uint32_t en) {
    asm volatile(
        "{\n\t.reg .pred p;\n\t"
        "setp.ne.u32 p, %4, 0;\n\t"
        "tcgen05.mma.cta_group::1.kind::tf32 [%0], %1, %2, %3, {%5, %5, %5, %5}, p;\n\t}"
        :: "r"(d), "l"(ad), "l"(bd), "r"(idesc), "r"(en), "r"(0u) : "memory");
}
__device__ __forceinline__ void mbar_wait(uint32_t m, uint32_t par) {
    asm volatile(
        "{\n\t.reg .pred P;\n\t"
        "WL%=:\n\t"
        "mbarrier.try_wait.parity.acquire.cta.shared::cta.b64 P, [%0], %1, 0x989680;\n\t"
        "@!P bra WL%=;\n\t}"
        :: "r"(m), "r"(par) : "memory");
}
#endif

// ---------------------------------------------------------------------------
// mRoPE cos/sin table
// ---------------------------------------------------------------------------
__global__ void cossin_kernel(const int* __restrict__ pos,
                              float* __restrict__ cosb,
                              float* __restrict__ sinb) {
    int idx = blockIdx.x * blockDim.x + threadIdx.x;
    if (idx >= Bc * Sc * HDc) return;
    int d  = idx & 63;
    int bs = idx >> 6;
    int i  = d & 31;
    int sec = (i < 16) ? 0 : 1;
    float p = (float)pos[sec * (Bc * Sc) + bs];
    float inv_freq = exp2f(-0.6228615177913804f * (float)i);
    float ang = p * inv_freq;
    float s, c;
    sincosf(ang, &s, &c);
    cosb[idx] = c;
    sinb[idx] = s;
}

// ---------------------------------------------------------------------------
// RoPE
// ---------------------------------------------------------------------------
__global__ void rope_kernel(float* __restrict__ X,
                            const float* __restrict__ cosb,
                            const float* __restrict__ sinb,
                            int nheads, int total_pairs) {
    int idx = blockIdx.x * blockDim.x + threadIdx.x;
    if (idx >= total_pairs) return;
    int d    = idx & 31;
    int rest = idx >> 5;
    int bs   = rest / nheads;
    float* p = X + (size_t)rest * HDc;
    const float* cb = cosb + (size_t)bs * HDc;
    const float* sb = sinb + (size_t)bs * HDc;
    float x1 = p[d], x2 = p[d + 32];
    float c1 = cb[d], s1 = sb[d];
    float c2 = cb[d + 32], s2 = sb[d + 32];
    p[d]      = x1 * c1 - x2 * s1;
    p[d + 32] = x2 * c2 + x1 * s2;
}

// ---------------------------------------------------------------------------
// Weight transpose + tf32 hi/lo split: W[K,N] -> Th[N,K], Tl[N,K]
// ---------------------------------------------------------------------------
__global__ void wconv_kernel(const float* __restrict__ W,
                             float* __restrict__ Th, float* __restrict__ Tl,
                             int K, int N) {
    __shared__ float t[32][33];
    int n0 = blockIdx.x * 32, k0 = blockIdx.y * 32;
    int c = threadIdx.x, r0 = threadIdx.y;          // block (32,8)
    #pragma unroll
    for (int i = 0; i < 4; i++) {
        int kk = r0 + i * 8;
        t[kk][c] = W[(size_t)(k0 + kk) * N + n0 + c];
    }
    __syncthreads();
    #pragma unroll
    for (int i = 0; i < 4; i++) {
        int nn = r0 + i * 8;
        float v = t[c][nn];
        float h = tf32_rn(v);
        float l = tf32_rn(v - h);
        size_t o = (size_t)(n0 + nn) * K + k0 + c;
        Th[o] = h;
        Tl[o] = l;
    }
}

// ---------------------------------------------------------------------------
// GEMM: C[M,N] = A[M,K] @ Bt^T  (Bt stored [N,K] split hi/lo) (+bias)
//  - sm_103a cubin: tcgen05 tf32x3, TMEM accumulator, double-buffered smem
//  - plain sm_103 cubin: fp32 FFMA 128x128x16 fallback (reads hi+lo)
// Same launch config for both paths.
// ---------------------------------------------------------------------------
#define GEMM_THREADS 256
#define SM_TMEMPTR 0
#define SM_MBAR    16
#define SM_TILES   1024
#define TILE_B     16384            // 128 rows x 128 bytes
#define BUF_B      (4 * TILE_B)     // Ah, Al, Bh, Bl
#define SM_STAGE   (SM_TILES + 2 * BUF_B)
#define SM_GTOTAL  (SM_STAGE + 128 * 33 * 4)

__global__ __launch_bounds__(GEMM_THREADS)
void tc_gemm(const float* __restrict__ A,
             const float* __restrict__ Bth, const float* __restrict__ Btl,
             const float* __restrict__ bias, float* __restrict__ C,
             int N, int K) {
    extern __shared__ char sm[];
    int tid = threadIdx.x;
    int m0 = blockIdx.y * 128, n0 = blockIdx.x * 128;

#if HAS_TCGEN05
    // ============================ tcgen05 path ============================
    uint32_t sb = smem_u32(sm);
    if (tid == 0) {
        asm volatile("mbarrier.init.shared.b64 [%0], 1;" :: "r"(sb + SM_MBAR) : "memory");
        asm volatile("mbarrier.init.shared.b64 [%0], 1;" :: "r"(sb + SM_MBAR + 8) : "memory");
    }
    if (tid < 32) {
        asm volatile("tcgen05.alloc.cta_group::1.sync.aligned.shared::cta.b32 [%0], %1;"
                     :: "r"(sb + SM_TMEMPTR), "r"(128u) : "memory");
        asm volatile("tcgen05.relinquish_alloc_permit.cta_group::1.sync.aligned;");
    }
    __syncthreads();
    uint32_t tmem;
    asm volatile("ld.shared.b32 %0, [%1];" : "=r"(tmem) : "r"(sb + SM_TMEMPTR));

    const uint32_t idesc = (1u << 4)            // D dtype = F32
                         | (2u << 7)            // A type = TF32
                         | (2u << 10)           // B type = TF32
                         | ((128u / 8) << 17)   // N
                         | ((128u / 16) << 24); // M
    const int NC = K >> 5;                      // 32-wide K chunks

    auto load_tiles = [&](int buf, int k0) {
        char* base = sm + SM_TILES + (size_t)buf * BUF_B;
        #pragma unroll
        for (int i = 0; i < 4; i++) {
            int idx = tid + i * 256;
            int r = idx >> 3, c4 = idx & 7;
            float4 v = *(const float4*)(A + (size_t)(m0 + r) * K + k0 + c4 * 4);
            float4 h, l;
            h.x = tf32_rn(v.x); l.x = tf32_rn(v.x - h.x);
            h.y = tf32_rn(v.y); l.y = tf32_rn(v.y - h.y);
            h.z = tf32_rn(v.z); l.z = tf32_rn(v.z - h.z);
            h.w = tf32_rn(v.w); l.w = tf32_rn(v.w - h.w);
            uint32_t off = (uint32_t)(r * 128 + c4 * 16);
            off ^= (off >> 3) & 0x70;
            *(float4*)(base + off)          = h;
            *(float4*)(base + TILE_B + off) = l;
        }
        #pragma unroll
        for (int i = 0; i < 4; i++) {
            int idx = tid + i * 256;
            int r = idx >> 3, c4 = idx & 7;
            size_t go = (size_t)(n0 + r) * K + k0 + c4 * 4;
            float4 h = *(const float4*)(Bth + go);
            float4 l = *(const float4*)(Btl + go);
            uint32_t off = (uint32_t)(r * 128 + c4 * 16);
            off ^= (off >> 3) & 0x70;
            *(float4*)(base + 2 * TILE_B + off) = h;
            *(float4*)(base + 3 * TILE_B + off) = l;
        }
    };

    load_tiles(0, 0);
    int ph0 = 0, ph1 = 0;
    for (int c = 0; c < NC; ++c) {
        int cur = c & 1;
        __syncthreads();
        if (tid == 0) {
            asm volatile("fence.proxy.async.shared::cta;" ::: "memory");
            uint32_t tb = sb + SM_TILES + (uint32_t)cur * BUF_B;
            uint64_t ah = mk_desc(tb);
            uint64_t al = mk_desc(tb + TILE_B);
            uint64_t bh = mk_desc(tb + 2 * TILE_B);
            uint64_t bl = mk_desc(tb + 3 * TILE_B);
            #pragma unroll
            for (int ks = 0; ks < 4; ++ks) {
                uint32_t en0 = (c == 0 && ks == 0) ? 0u : 1u;
                mma_tf32(tmem, ah + ks * 2, bh + ks * 2, idesc, en0);  // hi*hi
                mma_tf32(tmem, ah + ks * 2, bl + ks * 2, idesc, 1u);   // hi*lo
                mma_tf32(tmem, al + ks * 2, bh + ks * 2, idesc, 1u);   // lo*hi
            }
            asm volatile(
                "tcgen05.commit.cta_group::1.mbarrier::arrive::one.shared::cluster.b64 [%0];"
                :: "r"(sb + SM_MBAR + (uint32_t)cur * 8) : "memory");
        }
        if (c + 1 < NC) {
            int nxt = cur ^ 1;
            if (c >= 1) {
                mbar_wait(sb + SM_MBAR + (uint32_t)nxt * 8, nxt ? ph1 : ph0);
                if (nxt) ph1 ^= 1; else ph0 ^= 1;
            }
            load_tiles(nxt, (c + 1) << 5);
        }
    }
    {
        int last = (NC - 1) & 1;
        mbar_wait(sb + SM_MBAR + (uint32_t)last * 8, last ? ph1 : ph0);
    }
    asm volatile("tcgen05.fence::after_thread_sync;" ::: "memory");
    __syncthreads();

    // epilogue: 4 col-groups of 32, staged via smem for coalesced stores
    float* stage = (float*)(sm + SM_STAGE);
    int wid = tid >> 5, lid = tid & 31;
    for (int g = 0; g < 4; ++g) {
        if (tid < 128) {
            uint32_t d[32];
            asm volatile(
                "tcgen05.ld.sync.aligned.32x32b.x32.b32 "
                "{%0, %1, %2, %3, %4, %5, %6, %7, "
                " %8, %9, %10, %11, %12, %13, %14, %15, "
                " %16, %17, %18, %19, %20, %21, %22, %23, "
                " %24, %25, %26, %27, %28, %29, %30, %31}, [%32];"
                : "=r"(d[0]),  "=r"(d[1]),  "=r"(d[2]),  "=r"(d[3]),
                  "=r"(d[4]),  "=r"(d[5]),  "=r"(d[6]),  "=r"(d[7]),
                  "=r"(d[8]),  "=r"(d[9]),  "=r"(d[10]), "=r"(d[11]),
                  "=r"(d[12]), "=r"(d[13]), "=r"(d[14]), "=r"(d[15]),
                  "=r"(d[16]), "=r"(d[17]), "=r"(d[18]), "=r"(d[19]),
                  "=r"(d[20]), "=r"(d[21]), "=r"(d[22]), "=r"(d[23]),
                  "=r"(d[24]), "=r"(d[25]), "=r"(d[26]), "=r"(d[27]),
                  "=r"(d[28]), "=r"(d[29]), "=r"(d[30]), "=r"(d[31])
                : "r"(tmem + (uint32_t)g * 32));
            asm volatile("tcgen05.wait::ld.sync.aligned;" ::: "memory");
            int row = wid * 32 + lid;
            #pragma unroll
            for (int j = 0; j < 32; ++j)
                stage[row * 33 + j] = __uint_as_float(d[j]);
        }
        __syncthreads();
        #pragma unroll
        for (int i = 0; i < 4; ++i) {
            int rr = (tid >> 3) + i * 32;
            int c4 = tid & 7;
            float x0 = stage[rr * 33 + c4 * 4 + 0];
            float x1 = stage[rr * 33 + c4 * 4 + 1];
            float x2 = stage[rr * 33 + c4 * 4 + 2];
            float x3 = stage[rr * 33 + c4 * 4 + 3];
            int n = n0 + g * 32 + c4 * 4;
            if (bias) {
                x0 += bias[n + 0]; x1 += bias[n + 1];
                x2 += bias[n + 2]; x3 += bias[n + 3];
            }
            float4 o = make_float4(x0, x1, x2, x3);
            *(float4*)(C + (size_t)(m0 + rr) * N + n) = o;
        }
        __syncthreads();
    }

    if (tid < 32) {
        asm volatile("tcgen05.dealloc.cta_group::1.sync.aligned.b32 %0, %1;"
                     :: "r"(tmem), "r"(128u));
    }
#else
    // ============================ FFMA fallback ============================
    // 128x128 tile, BK=16, 8x8 microtile. A is [M,K]; Bt is [N,K] hi/lo split.
    float (*As)[128] = (float (*)[128])(sm);            // [16][128]
    float (*Bs)[128] = (float (*)[128])(sm + 8192);     // [16][128]

    int tcol = tid & 15;
    int trow = tid >> 4;

    float acc[8][8];
    #pragma unroll
    for (int i = 0; i < 8; i++)
        #pragma unroll
        for (int j = 0; j < 8; j++) acc[i][j] = 0.f;

    for (int k0 = 0; k0 < K; k0 += 16) {
        #pragma unroll
        for (int i = 0; i < 2; i++) {
            int idx = tid + i * 256;     // 0..511 float4s
            int r  = idx >> 2;           // row 0..127
            int c4 = idx & 3;            // f4 col 0..3
            float4 va = *(const float4*)(A + (size_t)(m0 + r) * K + k0 + c4 * 4);
            As[c4 * 4 + 0][r] = va.x;
            As[c4 * 4 + 1][r] = va.y;
            As[c4 * 4 + 2][r] = va.z;
            As[c4 * 4 + 3][r] = va.w;
            size_t go = (size_t)(n0 + r) * K + k0 + c4 * 4;
            float4 vh = *(const float4*)(Bth + go);
            float4 vl = *(const float4*)(Btl + go);
            Bs[c4 * 4 + 0][r] = vh.x + vl.x;
            Bs[c4 * 4 + 1][r] = vh.y + vl.y;
            Bs[c4 * 4 + 2][r] = vh.z + vl.z;
            Bs[c4 * 4 + 3][r] = vh.w + vl.w;
        }
        __syncthreads();

        #pragma unroll
        for (int kk = 0; kk < 16; kk++) {
            float ra[8], rb[8];
            *(float4*)&ra[0] = *(const float4*)&As[kk][trow * 8];
            *(float4*)&ra[4] = *(const float4*)&As[kk][trow * 8 + 4];
            *(float4*)&rb[0] = *(const float4*)&Bs[kk][tcol * 8];
            *(float4*)&rb[4] = *(const float4*)&Bs[kk][tcol * 8 + 4];
            #pragma unroll
            for (int i = 0; i < 8; i++)
                #pragma unroll
                for (int j = 0; j < 8; j++)
                    acc[i][j] = fmaf(ra[i], rb[j], acc[i][j]);
        }
        __syncthreads();
    }

    #pragma unroll
    for (int i = 0; i < 8; i++) {
        int m = m0 + trow * 8 + i;
        float* crow = C + (size_t)m * N + n0 + tcol * 8;
        #pragma unroll
        for (int jj = 0; jj < 8; jj += 4) {
            int n = n0 + tcol * 8 + jj;
            float4 v;
            v.x = acc[i][jj + 0];
            v.y = acc[i][jj + 1];
            v.z = acc[i][jj + 2];
            v.w = acc[i][jj + 3];
            if (bias) {
                v.x += bias[n + 0]; v.y += bias[n + 1];
                v.z += bias[n + 2]; v.w += bias[n + 3];
            }
            *(float4*)(crow + jj) = v;
        }
    }
#endif
}

// ---------------------------------------------------------------------------
// Flash-style causal attention
// ---------------------------------------------------------------------------
__device__ __forceinline__ float fast_exp2(float x) {
    float y;
    asm("ex2.approx.ftz.f32 %0, %1;" : "=f"(y) : "f"(x));
    return y;
}

#define AQB 128
#define AKB 32

__global__ __launch_bounds__(AQB)
void attn_kernel(const float* __restrict__ Q, const float* __restrict__ Kg,
                 const float* __restrict__ Vg, float* __restrict__ O) {
    int qb = blockIdx.x, h = blockIdx.y, b = blockIdx.z;
    int kh = h >> 2;
    int tid = threadIdx.x;
    int qi = qb * AQB + tid;

    __shared__ __align__(16) float Ks[AKB][HDc];
    __shared__ __align__(16) float Vs[AKB][HDc];

    const float SCALE = 0.125f * 1.4426950408889634f;
    float q[HDc];
    {
        const float4* qp = (const float4*)(Q + ((size_t)(b * Sc + qi) * NHc + h) * HDc);
        #pragma unroll
        for (int d4 = 0; d4 < 16; d4++) {
            float4 v = qp[d4];
            q[d4 * 4 + 0] = v.x * SCALE;
            q[d4 * 4 + 1] = v.y * SCALE;
            q[d4 * 4 + 2] = v.z * SCALE;
            q[d4 * 4 + 3] = v.w * SCALE;
        }
    }

    float o[HDc];
    #pragma unroll
    for (int d = 0; d < HDc; d++) o[d] = 0.f;
    float m = -1e30f, l = 0.f;

    int ntiles = ((qb + 1) * AQB) / AKB;

    for (int kt = 0; kt < ntiles; kt++) {
        int kbase = kt * AKB;
        __syncthreads();
        #pragma unroll
        for (int i = 0; i < 4; i++) {
            int idx = tid + i * AQB;
            int r  = idx >> 4;
            int c4 = idx & 15;
            size_t roff = ((size_t)(b * Sc + kbase + r) * NKVc + kh) * HDc;
            ((float4*)&Ks[r][0])[c4] = ((const float4*)(Kg + roff))[c4];
            ((float4*)&Vs[r][0])[c4] = ((const float4*)(Vg + roff))[c4];
        }
        __syncthreads();

        #pragma unroll 1
        for (int c = 0; c < AKB; c += 4) {
            float s0 = 0.f, s1 = 0.f, s2 = 0.f, s3 = 0.f;
            const float4* K0 = (const float4*)&Ks[c + 0][0];
            const float4* K1 = (const float4*)&Ks[c + 1][0];
            const float4* K2 = (const float4*)&Ks[c + 2][0];
            const float4* K3 = (const float4*)&Ks[c + 3][0];
            #pragma unroll
            for (int d4 = 0; d4 < 16; d4++) {
                float4 a = K0[d4], e = K1[d4], f = K2[d4], g = K3[d4];
                float q0 = q[d4 * 4 + 0], q1 = q[d4 * 4 + 1];
                float q2 = q[d4 * 4 + 2], q3 = q[d4 * 4 + 3];
                s0 = fmaf(q0, a.x, s0); s0 = fmaf(q1, a.y, s0);
                s0 = fmaf(q2, a.z, s0); s0 = fmaf(q3, a.w, s0);
                s1 = fmaf(q0, e.x, s1); s1 = fmaf(q1, e.y, s1);
                s1 = fmaf(q2, e.z, s1); s1 = fmaf(q3, e.w, s1);
                s2 = fmaf(q0, f.x, s2); s2 = fmaf(q1, f.y, s2);
                s2 = fmaf(q2, f.z, s2); s2 = fmaf(q3, f.w, s2);
                s3 = fmaf(q0, g.x, s3); s3 = fmaf(q1, g.y, s3);
                s3 = fmaf(q2, g.z, s3); s3 = fmaf(q3, g.w, s3);
            }
            int kg = kbase + c;
            s0 = (kg + 0 <= qi) ? s0 : -1e30f;
            s1 = (kg + 1 <= qi) ? s1 : -1e30f;
            s2 = (kg + 2 <= qi) ? s2 : -1e30f;
            s3 = (kg + 3 <= qi) ? s3 : -1e30f;

            float m4 = fmaxf(fmaxf(s0, s1), fmaxf(s2, s3));
            if (m4 > m) {
                float sc = fast_exp2(m - m4);
                l *= sc;
                #pragma unroll
                for (int d = 0; d < HDc; d++) o[d] *= sc;
                m = m4;
            }
            float p0 = fast_exp2(s0 - m);
            float p1 = fast_exp2(s1 - m);
            float p2 = fast_exp2(s2 - m);
            float p3 = fast_exp2(s3 - m);
            l += (p0 + p1) + (p2 + p3);

            const float4* V0 = (const float4*)&Vs[c + 0][0];
            const float4* V1 = (const float4*)&Vs[c + 1][0];
            const float4* V2 = (const float4*)&Vs[c + 2][0];
            const float4* V3 = (const float4*)&Vs[c + 3][0];
            #pragma unroll
            for (int d4 = 0; d4 < 16; d4++) {
                float4 a = V0[d4], e = V1[d4], f = V2[d4], g = V3[d4];
                o[d4*4+0] = fmaf(p0, a.x, fmaf(p1, e.x, fmaf(p2, f.x, fmaf(p3, g.x, o[d4*4+0]))));
                o[d4*4+1] = fmaf(p0, a.y, fmaf(p1, e.y, fmaf(p2, f.y, fmaf(p3, g.y, o[d4*4+1]))));
                o[d4*4+2] = fmaf(p0, a.z, fmaf(p1, e.z, fmaf(p2, f.z, fmaf(p3, g.z, o[d4*4+2]))));
                o[d4*4+3] = fmaf(p0, a.w, fmaf(p1, e.w, fmaf(p2, f.w, fmaf(p3, g.w, o[d4*4+3]))));
            }
        }
    }

    float inv_l = 1.0f / l;
    float4* op = (float4*)(O + ((size_t)(b * Sc + qi) * NHc + h) * HDc);
    #pragma unroll
    for (int d4 = 0; d4 < 16; d4++) {
        float4 v;
        v.x = o[d4 * 4 + 0] * inv_l;
        v.y = o[d4 * 4 + 1] * inv_l;
        v.z = o[d4 * 4 + 2] * inv_l;
        v.w = o[d4 * 4 + 3] * inv_l;
        op[d4] = v;
    }
}

// ---------------------------------------------------------------------------
// launch
// ---------------------------------------------------------------------------
extern "C" void kernel_launch(void* const* d_in, const int* in_sizes, int n_in,
                              void* d_out, int out_size) {
    (void)in_sizes; (void)n_in; (void)out_size;
    const float* x   = (const float*)d_in[0];
    const int*   pos = (const int*)  d_in[1];
    const float* Wq  = (const float*)d_in[2];
    const float* bq  = (const float*)d_in[3];
    const float* Wk  = (const float*)d_in[4];
    const float* bk  = (const float*)d_in[5];
    const float* Wv  = (const float*)d_in[6];
    const float* bv  = (const float*)d_in[7];
    const float* Wo  = (const float*)d_in[8];
    float* out = (float*)d_out;

    float *q, *k, *v, *att, *cs, *sn;
    float *wqh, *wql, *wkh, *wkl, *wvh, *wvl, *woh, *wol;
    cudaGetSymbolAddress((void**)&q,   g_q);
    cudaGetSymbolAddress((void**)&k,   g_k);
    cudaGetSymbolAddress((void**)&v,   g_v);
    cudaGetSymbolAddress((void**)&att, g_att);
    cudaGetSymbolAddress((void**)&cs,  g_cos);
    cudaGetSymbolAddress((void**)&sn,  g_sin);
    cudaGetSymbolAddress((void**)&wqh, g_wqh);
    cudaGetSymbolAddress((void**)&wql, g_wql);
    cudaGetSymbolAddress((void**)&wkh, g_wkh);
    cudaGetSymbolAddress((void**)&wkl, g_wkl);
    cudaGetSymbolAddress((void**)&wvh, g_wvh);
    cudaGetSymbolAddress((void**)&wvl, g_wvl);
    cudaGetSymbolAddress((void**)&woh, g_woh);
    cudaGetSymbolAddress((void**)&wol, g_wol);

    cudaFuncSetAttribute(tc_gemm, cudaFuncAttributeMaxDynamicSharedMemorySize, SM_GTOTAL);

    // 0) weight transpose + tf32 split
    dim3 tb(32, 8);
    wconv_kernel<<<dim3(2048 / 32, 2048 / 32), tb>>>(Wq, wqh, wql, 2048, 2048);
    wconv_kernel<<<dim3(512  / 32, 2048 / 32), tb>>>(Wk, wkh, wkl, 2048, 512);
    wconv_kernel<<<dim3(512  / 32, 2048 / 32), tb>>>(Wv, wvh, wvl, 2048, 512);
    wconv_kernel<<<dim3(2048 / 32, 2048 / 32), tb>>>(Wo, woh, wol, 2048, 2048);

    // 1) rotary tables
    cossin_kernel<<<(Bc * Sc * HDc + 255) / 256, 256>>>(pos, cs, sn);

    // 2) QKV projections
    tc_gemm<<<dim3(2048 / 128, MQ / 128), GEMM_THREADS, SM_GTOTAL>>>(x, wqh, wql, bq, q, 2048, Hc);
    tc_gemm<<<dim3(512  / 128, MQ / 128), GEMM_THREADS, SM_GTOTAL>>>(x, wkh, wkl, bk, k, 512,  Hc);
    tc_gemm<<<dim3(512  / 128, MQ / 128), GEMM_THREADS, SM_GTOTAL>>>(x, wvh, wvl, bv, v, 512,  Hc);

    // 3) RoPE on q and k
    rope_kernel<<<(Bc * Sc * NHc * 32 + 255) / 256, 256>>>(q, cs, sn, NHc, Bc * Sc * NHc * 32);
    rope_kernel<<<(Bc * Sc * NKVc * 32 + 255) / 256, 256>>>(k, cs, sn, NKVc, Bc * Sc * NKVc * 32);

    // 4) causal GQA attention
    attn_kernel<<<dim3(Sc / AQB, NHc, Bc), AQB>>>(q, k, v, att);

    // 5) output projection
    tc_gemm<<<dim3(2048 / 128, MQ / 128), GEMM_THREADS, SM_GTOTAL>>>(att, woh, wol, nullptr, out, 2048, Hc);
}

// round 4
// speedup vs baseline: 2.2795x; 1.6126x over previous
#include <cuda_runtime.h>
#include <math.h>
#include <stdint.h>

// Problem constants
#define Bc   2
#define Sc   2048
#define Hc   2048
#define NHc  32
#define NKVc 8
#define HDc  64
#define MQ   (Bc * Sc)          // 4096 rows

#if defined(__CUDA_ARCH__) && defined(__CUDA_ARCH_FEAT_SM103_ALL)
#define HAS_TCGEN05 1
#else
#define HAS_TCGEN05 0
#endif

// ---------------------------------------------------------------------------
// Scratch (device globals)
// ---------------------------------------------------------------------------
__device__ float g_q  [(size_t)Bc * Sc * NHc  * HDc];
__device__ float g_k  [(size_t)Bc * Sc * NKVc * HDc];
__device__ float g_v  [(size_t)Bc * Sc * NKVc * HDc];
__device__ float g_vt [(size_t)Bc * NKVc * HDc * Sc];   // V transposed [b,kv,d,s]
__device__ float g_att[(size_t)Bc * Sc * NHc  * HDc];
__device__ float g_cos[(size_t)Bc * Sc * HDc];
__device__ float g_sin[(size_t)Bc * Sc * HDc];
// transposed + tf32-split weights: [N, K] row-major
__device__ float g_wqh[(size_t)2048 * 2048], g_wql[(size_t)2048 * 2048];
__device__ float g_wkh[(size_t)512  * 2048], g_wkl[(size_t)512  * 2048];
__device__ float g_wvh[(size_t)512  * 2048], g_wvl[(size_t)512  * 2048];
__device__ float g_woh[(size_t)2048 * 2048], g_wol[(size_t)2048 * 2048];

// ---------------------------------------------------------------------------
// small helpers
// ---------------------------------------------------------------------------
__device__ __forceinline__ uint32_t smem_u32(const void* p) {
    uint32_t a;
    asm("{ .reg .u64 t; cvta.to.shared.u64 t, %1; cvt.u32.u64 %0, t; }" : "=r"(a) : "l"(p));
    return a;
}
__device__ __forceinline__ float tf32_rn(float a) {
    uint32_t u;
    asm("cvt.rna.tf32.f32 %0, %1;" : "=r"(u) : "f"(a));
    return __uint_as_float(u);
}
__device__ __forceinline__ float fast_exp2(float x) {
    float y;
    asm("ex2.approx.ftz.f32 %0, %1;" : "=f"(y) : "f"(x));
    return y;
}

#if HAS_TCGEN05
__device__ __forceinline__ uint64_t mk_desc(uint32_t addr) {
    // SW128, version=1 (Blackwell), SBO=64, LBO=1, start=addr>>4
    return ((uint64_t)2 << 61) | ((uint64_t)1 << 46) | ((uint64_t)64 << 32) |
           ((uint64_t)1 << 16) | ((uint64_t)((addr >> 4) & 0x3FFF));
}
__device__ __forceinline__ void mma_tf32(uint32_t d, uint64_t ad, uint64_t bd,
                                         uint32_t idesc, uint32_t en) {
    asm volatile(
        "{\n\t.reg .pred p;\n\t"
        "setp.ne.u32 p, %4, 0;\n\t"
        "tcgen05.mma.cta_group::1.kind::tf32 [%0], %1, %2, %3, {%5, %5, %5, %5}, p;\n\t}"
        :: "r"(d), "l"(ad), "l"(bd), "r"(idesc), "r"(en), "r"(0u) : "memory");
}
__device__ __forceinline__ void mma_tf32_ts(uint32_t d, uint32_t a, uint64_t bd,
                                            uint32_t idesc, uint32_t en) {
    asm volatile(
        "{\n\t.reg .pred p;\n\t"
        "setp.ne.u32 p, %4, 0;\n\t"
        "tcgen05.mma.cta_group::1.kind::tf32 [%0], [%1], %2, %3, {%5, %5, %5, %5}, p;\n\t}"
        :: "r"(d), "r"(a), "l"(bd), "r"(idesc), "r"(en), "r"(0u) : "memory");
}
__device__ __forceinline__ void mbar_wait(uint32_t m, uint32_t par) {
    asm volatile(
        "{\n\t.reg .pred P;\n\t"
        "WL%=:\n\t"
        "mbarrier.try_wait.parity.acquire.cta.shared::cta.b64 P, [%0], %1, 0x989680;\n\t"
        "@!P bra WL%=;\n\t}"
        :: "r"(m), "r"(par) : "memory");
}
__device__ __forceinline__ void ldtm32(uint32_t* r, uint32_t addr) {
    asm volatile(
        "tcgen05.ld.sync.aligned.32x32b.x32.b32 "
        "{%0, %1, %2, %3, %4, %5, %6, %7, "
        " %8, %9, %10, %11, %12, %13, %14, %15, "
        " %16, %17, %18, %19, %20, %21, %22, %23, "
        " %24, %25, %26, %27, %28, %29, %30, %31}, [%32];"
        : "=r"(r[0]),  "=r"(r[1]),  "=r"(r[2]),  "=r"(r[3]),
          "=r"(r[4]),  "=r"(r[5]),  "=r"(r[6]),  "=r"(r[7]),
          "=r"(r[8]),  "=r"(r[9]),  "=r"(r[10]), "=r"(r[11]),
          "=r"(r[12]), "=r"(r[13]), "=r"(r[14]), "=r"(r[15]),
          "=r"(r[16]), "=r"(r[17]), "=r"(r[18]), "=r"(r[19]),
          "=r"(r[20]), "=r"(r[21]), "=r"(r[22]), "=r"(r[23]),
          "=r"(r[24]), "=r"(r[25]), "=r"(r[26]), "=r"(r[27]),
          "=r"(r[28]), "=r"(r[29]), "=r"(r[30]), "=r"(r[31])
        : "r"(addr));
}
__device__ __forceinline__ void sttm32(uint32_t addr, const uint32_t* r) {
    asm volatile(
        "tcgen05.st.sync.aligned.32x32b.x32.b32 [%0], "
        "{%1, %2, %3, %4, %5, %6, %7, %8, "
        " %9, %10, %11, %12, %13, %14, %15, %16, "
        " %17, %18, %19, %20, %21, %22, %23, %24, "
        " %25, %26, %27, %28, %29, %30, %31, %32};"
        :: "r"(addr),
           "r"(r[0]),  "r"(r[1]),  "r"(r[2]),  "r"(r[3]),
           "r"(r[4]),  "r"(r[5]),  "r"(r[6]),  "r"(r[7]),
           "r"(r[8]),  "r"(r[9]),  "r"(r[10]), "r"(r[11]),
           "r"(r[12]), "r"(r[13]), "r"(r[14]), "r"(r[15]),
           "r"(r[16]), "r"(r[17]), "r"(r[18]), "r"(r[19]),
           "r"(r[20]), "r"(r[21]), "r"(r[22]), "r"(r[23]),
           "r"(r[24]), "r"(r[25]), "r"(r[26]), "r"(r[27]),
           "r"(r[28]), "r"(r[29]), "r"(r[30]), "r"(r[31])
        : "memory");
}
#endif

// ---------------------------------------------------------------------------
// mRoPE cos/sin table
// ---------------------------------------------------------------------------
__global__ void cossin_kernel(const int* __restrict__ pos,
                              float* __restrict__ cosb,
                              float* __restrict__ sinb) {
    int idx = blockIdx.x * blockDim.x + threadIdx.x;
    if (idx >= Bc * Sc * HDc) return;
    int d  = idx & 63;
    int bs = idx >> 6;
    int i  = d & 31;
    int sec = (i < 16) ? 0 : 1;
    float p = (float)pos[sec * (Bc * Sc) + bs];
    float inv_freq = exp2f(-0.6228615177913804f * (float)i);
    float ang = p * inv_freq;
    float s, c;
    sincosf(ang, &s, &c);
    cosb[idx] = c;
    sinb[idx] = s;
}

// ---------------------------------------------------------------------------
// RoPE
// ---------------------------------------------------------------------------
__global__ void rope_kernel(float* __restrict__ X,
                            const float* __restrict__ cosb,
                            const float* __restrict__ sinb,
                            int nheads, int total_pairs) {
    int idx = blockIdx.x * blockDim.x + threadIdx.x;
    if (idx >= total_pairs) return;
    int d    = idx & 31;
    int rest = idx >> 5;
    int bs   = rest / nheads;
    float* p = X + (size_t)rest * HDc;
    const float* cb = cosb + (size_t)bs * HDc;
    const float* sb = sinb + (size_t)bs * HDc;
    float x1 = p[d], x2 = p[d + 32];
    float c1 = cb[d], s1 = sb[d];
    float c2 = cb[d + 32], s2 = sb[d + 32];
    p[d]      = x1 * c1 - x2 * s1;
    p[d + 32] = x2 * c2 + x1 * s2;
}

// ---------------------------------------------------------------------------
// Weight transpose + tf32 hi/lo split: W[K,N] -> Th[N,K], Tl[N,K]
// ---------------------------------------------------------------------------
__global__ void wconv_kernel(const float* __restrict__ W,
                             float* __restrict__ Th, float* __restrict__ Tl,
                             int K, int N) {
    __shared__ float t[32][33];
    int n0 = blockIdx.x * 32, k0 = blockIdx.y * 32;
    int c = threadIdx.x, r0 = threadIdx.y;          // block (32,8)
    #pragma unroll
    for (int i = 0; i < 4; i++) {
        int kk = r0 + i * 8;
        t[kk][c] = W[(size_t)(k0 + kk) * N + n0 + c];
    }
    __syncthreads();
    #pragma unroll
    for (int i = 0; i < 4; i++) {
        int nn = r0 + i * 8;
        float v = t[c][nn];
        float h = tf32_rn(v);
        float l = tf32_rn(v - h);
        size_t o = (size_t)(n0 + nn) * K + k0 + c;
        Th[o] = h;
        Tl[o] = l;
    }
}

// ---------------------------------------------------------------------------
// V transpose: v[b,s,kv,64] -> vt[b,kv,64,s]
// ---------------------------------------------------------------------------
__global__ void vtrans_kernel(const float* __restrict__ V, float* __restrict__ VT) {
    __shared__ float t[32][33];
    int s0 = blockIdx.x * 32, d0 = blockIdx.y * 32;
    int bkv = blockIdx.z;                    // b*NKV + kv
    int b = bkv >> 3, kv = bkv & 7;
    int c = threadIdx.x, r0 = threadIdx.y;   // block (32,8)
    #pragma unroll
    for (int i = 0; i < 4; i++) {
        int ss = r0 + i * 8;
        t[ss][c] = V[(((size_t)(b * Sc + s0 + ss)) * NKVc + kv) * HDc + d0 + c];
    }
    __syncthreads();
    #pragma unroll
    for (int i = 0; i < 4; i++) {
        int dd = r0 + i * 8;
        VT[((size_t)bkv * HDc + d0 + dd) * Sc + s0 + c] = t[c][dd];
    }
}

// ---------------------------------------------------------------------------
// GEMM: C[M,N] = A[M,K] @ Bt^T  (Bt stored [N,K] split hi/lo) (+bias)
//  - sm_103a cubin: tcgen05 tf32x3; plain sm_103 cubin: FFMA fallback
// ---------------------------------------------------------------------------
#define GEMM_THREADS 256
#define SM_TMEMPTR 0
#define SM_MBAR    16
#define SM_TILES   1024
#define TILE_B     16384            // 128 rows x 128 bytes
#define BUF_B      (4 * TILE_B)     // Ah, Al, Bh, Bl
#define SM_STAGE   (SM_TILES + 2 * BUF_B)
#define SM_GTOTAL  (SM_STAGE + 128 * 33 * 4)

__global__ __launch_bounds__(GEMM_THREADS)
void tc_gemm(const float* __restrict__ A,
             const float* __restrict__ Bth, const float* __restrict__ Btl,
             const float* __restrict__ bias, float* __restrict__ C,
             int N, int K) {
    extern __shared__ char sm[];
    int tid = threadIdx.x;
    int m0 = blockIdx.y * 128, n0 = blockIdx.x * 128;

#if HAS_TCGEN05
    uint32_t sb = smem_u32(sm);
    if (tid == 0) {
        asm volatile("mbarrier.init.shared.b64 [%0], 1;" :: "r"(sb + SM_MBAR) : "memory");
        asm volatile("mbarrier.init.shared.b64 [%0], 1;" :: "r"(sb + SM_MBAR + 8) : "memory");
    }
    if (tid < 32) {
        asm volatile("tcgen05.alloc.cta_group::1.sync.aligned.shared::cta.b32 [%0], %1;"
                     :: "r"(sb + SM_TMEMPTR), "r"(128u) : "memory");
        asm volatile("tcgen05.relinquish_alloc_permit.cta_group::1.sync.aligned;");
    }
    __syncthreads();
    uint32_t tmem;
    asm volatile("ld.shared.b32 %0, [%1];" : "=r"(tmem) : "r"(sb + SM_TMEMPTR));

    const uint32_t idesc = (1u << 4) | (2u << 7) | (2u << 10)
                         | ((128u / 8) << 17) | ((128u / 16) << 24);
    const int NC = K >> 5;

    auto load_tiles = [&](int buf, int k0) {
        char* base = sm + SM_TILES + (size_t)buf * BUF_B;
        #pragma unroll
        for (int i = 0; i < 4; i++) {
            int idx = tid + i * 256;
            int r = idx >> 3, c4 = idx & 7;
            float4 v = *(const float4*)(A + (size_t)(m0 + r) * K + k0 + c4 * 4);
            float4 h, l;
            h.x = tf32_rn(v.x); l.x = tf32_rn(v.x - h.x);
            h.y = tf32_rn(v.y); l.y = tf32_rn(v.y - h.y);
            h.z = tf32_rn(v.z); l.z = tf32_rn(v.z - h.z);
            h.w = tf32_rn(v.w); l.w = tf32_rn(v.w - h.w);
            uint32_t off = (uint32_t)(r * 128 + c4 * 16);
            off ^= (off >> 3) & 0x70;
            *(float4*)(base + off)          = h;
            *(float4*)(base + TILE_B + off) = l;
        }
        #pragma unroll
        for (int i = 0; i < 4; i++) {
            int idx = tid + i * 256;
            int r = idx >> 3, c4 = idx & 7;
            size_t go = (size_t)(n0 + r) * K + k0 + c4 * 4;
            float4 h = *(const float4*)(Bth + go);
            float4 l = *(const float4*)(Btl + go);
            uint32_t off = (uint32_t)(r * 128 + c4 * 16);
            off ^= (off >> 3) & 0x70;
            *(float4*)(base + 2 * TILE_B + off) = h;
            *(float4*)(base + 3 * TILE_B + off) = l;
        }
    };

    load_tiles(0, 0);
    int ph0 = 0, ph1 = 0;
    for (int c = 0; c < NC; ++c) {
        int cur = c & 1;
        __syncthreads();
        if (tid == 0) {
            asm volatile("fence.proxy.async.shared::cta;" ::: "memory");
            uint32_t tb = sb + SM_TILES + (uint32_t)cur * BUF_B;
            uint64_t ah = mk_desc(tb);
            uint64_t al = mk_desc(tb + TILE_B);
            uint64_t bh = mk_desc(tb + 2 * TILE_B);
            uint64_t bl = mk_desc(tb + 3 * TILE_B);
            #pragma unroll
            for (int ks = 0; ks < 4; ++ks) {
                uint32_t en0 = (c == 0 && ks == 0) ? 0u : 1u;
                mma_tf32(tmem, ah + ks * 2, bh + ks * 2, idesc, en0);
                mma_tf32(tmem, ah + ks * 2, bl + ks * 2, idesc, 1u);
                mma_tf32(tmem, al + ks * 2, bh + ks * 2, idesc, 1u);
            }
            asm volatile(
                "tcgen05.commit.cta_group::1.mbarrier::arrive::one.shared::cluster.b64 [%0];"
                :: "r"(sb + SM_MBAR + (uint32_t)cur * 8) : "memory");
        }
        if (c + 1 < NC) {
            int nxt = cur ^ 1;
            if (c >= 1) {
                mbar_wait(sb + SM_MBAR + (uint32_t)nxt * 8, nxt ? ph1 : ph0);
                if (nxt) ph1 ^= 1; else ph0 ^= 1;
            }
            load_tiles(nxt, (c + 1) << 5);
        }
    }
    {
        int last = (NC - 1) & 1;
        mbar_wait(sb + SM_MBAR + (uint32_t)last * 8, last ? ph1 : ph0);
    }
    asm volatile("tcgen05.fence::after_thread_sync;" ::: "memory");
    __syncthreads();

    float* stage = (float*)(sm + SM_STAGE);
    int wid = tid >> 5, lid = tid & 31;
    for (int g = 0; g < 4; ++g) {
        if (tid < 128) {
            uint32_t d[32];
            ldtm32(d, tmem + (uint32_t)g * 32);
            asm volatile("tcgen05.wait::ld.sync.aligned;" ::: "memory");
            int row = wid * 32 + lid;
            #pragma unroll
            for (int j = 0; j < 32; ++j)
                stage[row * 33 + j] = __uint_as_float(d[j]);
        }
        __syncthreads();
        #pragma unroll
        for (int i = 0; i < 4; ++i) {
            int rr = (tid >> 3) + i * 32;
            int c4 = tid & 7;
            float x0 = stage[rr * 33 + c4 * 4 + 0];
            float x1 = stage[rr * 33 + c4 * 4 + 1];
            float x2 = stage[rr * 33 + c4 * 4 + 2];
            float x3 = stage[rr * 33 + c4 * 4 + 3];
            int n = n0 + g * 32 + c4 * 4;
            if (bias) {
                x0 += bias[n + 0]; x1 += bias[n + 1];
                x2 += bias[n + 2]; x3 += bias[n + 3];
            }
            float4 o = make_float4(x0, x1, x2, x3);
            *(float4*)(C + (size_t)(m0 + rr) * N + n) = o;
        }
        __syncthreads();
    }

    if (tid < 32) {
        asm volatile("tcgen05.dealloc.cta_group::1.sync.aligned.b32 %0, %1;"
                     :: "r"(tmem), "r"(128u));
    }
#else
    // FFMA fallback
    float (*As)[128] = (float (*)[128])(sm);
    float (*Bs)[128] = (float (*)[128])(sm + 8192);
    int tcol = tid & 15;
    int trow = tid >> 4;
    float acc[8][8];
    #pragma unroll
    for (int i = 0; i < 8; i++)
        #pragma unroll
        for (int j = 0; j < 8; j++) acc[i][j] = 0.f;
    for (int k0 = 0; k0 < K; k0 += 16) {
        #pragma unroll
        for (int i = 0; i < 2; i++) {
            int idx = tid + i * 256;
            int r  = idx >> 2;
            int c4 = idx & 3;
            float4 va = *(const float4*)(A + (size_t)(m0 + r) * K + k0 + c4 * 4);
            As[c4 * 4 + 0][r] = va.x;
            As[c4 * 4 + 1][r] = va.y;
            As[c4 * 4 + 2][r] = va.z;
            As[c4 * 4 + 3][r] = va.w;
            size_t go = (size_t)(n0 + r) * K + k0 + c4 * 4;
            float4 vh = *(const float4*)(Bth + go);
            float4 vl = *(const float4*)(Btl + go);
            Bs[c4 * 4 + 0][r] = vh.x + vl.x;
            Bs[c4 * 4 + 1][r] = vh.y + vl.y;
            Bs[c4 * 4 + 2][r] = vh.z + vl.z;
            Bs[c4 * 4 + 3][r] = vh.w + vl.w;
        }
        __syncthreads();
        #pragma unroll
        for (int kk = 0; kk < 16; kk++) {
            float ra[8], rb[8];
            *(float4*)&ra[0] = *(const float4*)&As[kk][trow * 8];
            *(float4*)&ra[4] = *(const float4*)&As[kk][trow * 8 + 4];
            *(float4*)&rb[0] = *(const float4*)&Bs[kk][tcol * 8];
            *(float4*)&rb[4] = *(const float4*)&Bs[kk][tcol * 8 + 4];
            #pragma unroll
            for (int i = 0; i < 8; i++)
                #pragma unroll
                for (int j = 0; j < 8; j++)
                    acc[i][j] = fmaf(ra[i], rb[j], acc[i][j]);
        }
        __syncthreads();
    }
    #pragma unroll
    for (int i = 0; i < 8; i++) {
        int m = m0 + trow * 8 + i;
        float* crow = C + (size_t)m * N + n0 + tcol * 8;
        #pragma unroll
        for (int jj = 0; jj < 8; jj += 4) {
            int n = n0 + tcol * 8 + jj;
            float4 v;
            v.x = acc[i][jj + 0];
            v.y = acc[i][jj + 1];
            v.z = acc[i][jj + 2];
            v.w = acc[i][jj + 3];
            if (bias) {
                v.x += bias[n + 0]; v.y += bias[n + 1];
                v.z += bias[n + 2]; v.w += bias[n + 3];
            }
            *(float4*)(crow + jj) = v;
        }
    }
#endif
}

// ---------------------------------------------------------------------------
// Tensor-core causal GQA attention (tcgen05 tf32x3)
//  CTA = (128 q rows, one head). K-loop over 128-key tiles.
//  TMEM: S cols 0-127 | Phi 128-255 | Plo 256-383 | O 384-447
//  SMEM: Q hi/lo (64KB) | K hi/lo (64KB) | V^T hi/lo (64KB)
// ---------------------------------------------------------------------------
#define ATT_THREADS 256
#define AS_TMEM   0
#define AS_MQK    16
#define AS_MPV    24
#define AS_Q      1024
#define AS_K      (AS_Q + 65536)
#define AS_V      (AS_K + 65536)
#define AS_TOTAL  (AS_V + 65536 + 64)

__global__ __launch_bounds__(ATT_THREADS, 1)
void attn_tc(const float* __restrict__ Q, const float* __restrict__ Kg,
             const float* __restrict__ VT, float* __restrict__ O) {
    extern __shared__ char sm[];
    int tid = threadIdx.x;
    int qb = 15 - (int)blockIdx.x;          // big tiles first
    int h  = blockIdx.y, b = blockIdx.z;
    int kh = h >> 2;
    const float SCALE = 0.125f * 1.4426950408889634f;

#if HAS_TCGEN05
    uint32_t sb = smem_u32(sm);
    if (tid == 0) {
        asm volatile("mbarrier.init.shared.b64 [%0], 1;" :: "r"(sb + AS_MQK) : "memory");
        asm volatile("mbarrier.init.shared.b64 [%0], 1;" :: "r"(sb + AS_MPV) : "memory");
    }
    if (tid < 32) {
        asm volatile("tcgen05.alloc.cta_group::1.sync.aligned.shared::cta.b32 [%0], %1;"
                     :: "r"(sb + AS_TMEM), "r"(512u) : "memory");
        asm volatile("tcgen05.relinquish_alloc_permit.cta_group::1.sync.aligned;");
    }
    __syncthreads();
    uint32_t tmem;
    asm volatile("ld.shared.b32 %0, [%1];" : "=r"(tmem) : "r"(sb + AS_TMEM));

    const uint32_t IDQK = (1u << 4) | (2u << 7) | (2u << 10) | (16u << 17) | (8u << 24);
    const uint32_t IDPV = (1u << 4) | (2u << 7) | (2u << 10) | (8u  << 17) | (8u << 24);

    // ---- load Q tile (once): scale + tf32 split, SW128 subtiles ----
    {
        #pragma unroll
        for (int i = 0; i < 8; i++) {
            int idx = tid + i * 256;
            int r = idx >> 4, c4 = idx & 15;
            float4 v = *(const float4*)(Q + (((size_t)(b * Sc + qb * 128 + r)) * NHc + h) * HDc + c4 * 4);
            v.x *= SCALE; v.y *= SCALE; v.z *= SCALE; v.w *= SCALE;
            float4 hh, ll;
            hh.x = tf32_rn(v.x); ll.x = tf32_rn(v.x - hh.x);
            hh.y = tf32_rn(v.y); ll.y = tf32_rn(v.y - hh.y);
            hh.z = tf32_rn(v.z); ll.z = tf32_rn(v.z - hh.z);
            hh.w = tf32_rn(v.w); ll.w = tf32_rn(v.w - hh.w);
            int sub = c4 >> 3;
            uint32_t off = (uint32_t)(r * 128 + (c4 & 7) * 16);
            off ^= (off >> 3) & 0x70;
            *(float4*)(sm + AS_Q + sub * 16384 + off)         = hh;
            *(float4*)(sm + AS_Q + 32768 + sub * 16384 + off) = ll;
        }
    }

    float m_run = -1e30f, l_run = 0.f;
    uint32_t warp_off = ((uint32_t)(tid >> 5)) << 21;

    for (int i = 0; i <= qb; i++) {
        int kbase = i * 128;
        if (i > 0) mbar_wait(sb + AS_MPV, (i - 1) & 1);   // V smem, P/O TMEM free

        // ---- load K tile (split) and V^T tile (split) ----
        #pragma unroll
        for (int ii = 0; ii < 8; ii++) {
            int idx = tid + ii * 256;
            int r = idx >> 4, c4 = idx & 15;
            float4 v = *(const float4*)(Kg + (((size_t)(b * Sc + kbase + r)) * NKVc + kh) * HDc + c4 * 4);
            float4 hh, ll;
            hh.x = tf32_rn(v.x); ll.x = tf32_rn(v.x - hh.x);
            hh.y = tf32_rn(v.y); ll.y = tf32_rn(v.y - hh.y);
            hh.z = tf32_rn(v.z); ll.z = tf32_rn(v.z - hh.z);
            hh.w = tf32_rn(v.w); ll.w = tf32_rn(v.w - hh.w);
            int sub = c4 >> 3;
            uint32_t off = (uint32_t)(r * 128 + (c4 & 7) * 16);
            off ^= (off >> 3) & 0x70;
            *(float4*)(sm + AS_K + sub * 16384 + off)         = hh;
            *(float4*)(sm + AS_K + 32768 + sub * 16384 + off) = ll;
        }
        #pragma unroll
        for (int ii = 0; ii < 8; ii++) {
            int idx = tid + ii * 256;
            int d = idx >> 5, c4 = idx & 31;
            float4 v = *(const float4*)(VT + ((size_t)(b * NKVc + kh) * HDc + d) * Sc + kbase + c4 * 4);
            float4 hh, ll;
            hh.x = tf32_rn(v.x); ll.x = tf32_rn(v.x - hh.x);
            hh.y = tf32_rn(v.y); ll.y = tf32_rn(v.y - hh.y);
            hh.z = tf32_rn(v.z); ll.z = tf32_rn(v.z - hh.z);
            hh.w = tf32_rn(v.w); ll.w = tf32_rn(v.w - hh.w);
            int sub = c4 >> 3;
            uint32_t off = (uint32_t)(d * 128 + (c4 & 7) * 16);
            off ^= (off >> 3) & 0x70;
            *(float4*)(sm + AS_V + sub * 8192 + off)         = hh;
            *(float4*)(sm + AS_V + 32768 + sub * 8192 + off) = ll;
        }
        __syncthreads();

        // ---- QK MMA (tf32 x3) -> S ----
        if (tid == 0) {
            asm volatile("fence.proxy.async.shared::cta;" ::: "memory");
            uint64_t qh[2] = { mk_desc(sb + AS_Q),         mk_desc(sb + AS_Q + 16384) };
            uint64_t ql[2] = { mk_desc(sb + AS_Q + 32768), mk_desc(sb + AS_Q + 49152) };
            uint64_t khd[2] = { mk_desc(sb + AS_K),         mk_desc(sb + AS_K + 16384) };
            uint64_t kld[2] = { mk_desc(sb + AS_K + 32768), mk_desc(sb + AS_K + 49152) };
            bool first = true;
            #pragma unroll
            for (int sub = 0; sub < 2; sub++) {
                #pragma unroll
                for (int ks = 0; ks < 4; ks++) {
                    uint64_t a_h = qh[sub] + ks * 2, a_l = ql[sub] + ks * 2;
                    uint64_t b_h = khd[sub] + ks * 2, b_l = kld[sub] + ks * 2;
                    mma_tf32(tmem, a_h, b_h, IDQK, first ? 0u : 1u); first = false;
                    mma_tf32(tmem, a_h, b_l, IDQK, 1u);
                    mma_tf32(tmem, a_l, b_h, IDQK, 1u);
                }
            }
            asm volatile(
                "tcgen05.commit.cta_group::1.mbarrier::arrive::one.shared::cluster.b64 [%0];"
                :: "r"(sb + AS_MQK) : "memory");
        }

        // ---- softmax (warps 0-3, lane == q row) ----
        if (tid < 128) {
            int row = tid;
            mbar_wait(sb + AS_MQK, i & 1);
            asm volatile("tcgen05.fence::after_thread_sync;" ::: "memory");

            float s[128];
            #pragma unroll
            for (int ch = 0; ch < 4; ch++) {
                uint32_t r32[32];
                ldtm32(r32, tmem + (uint32_t)ch * 32);
                asm volatile("tcgen05.wait::ld.sync.aligned;" ::: "memory");
                #pragma unroll
                for (int j = 0; j < 32; j++) s[ch * 32 + j] = __uint_as_float(r32[j]);
            }
            if (i == qb) {
                #pragma unroll
                for (int j = 0; j < 128; j++)
                    if (j > row) s[j] = -1e30f;
            }
            float mx = m_run;
            #pragma unroll
            for (int j = 0; j < 128; j++) mx = fmaxf(mx, s[j]);

            float corr = fast_exp2(m_run - mx);
            if (i > 0) {
                #pragma unroll
                for (int g = 0; g < 2; g++) {
                    uint32_t o32[32];
                    ldtm32(o32, tmem + 384 + (uint32_t)g * 32);
                    asm volatile("tcgen05.wait::ld.sync.aligned;" ::: "memory");
                    #pragma unroll
                    for (int j = 0; j < 32; j++)
                        o32[j] = __float_as_uint(__uint_as_float(o32[j]) * corr);
                    sttm32(tmem + 384 + (uint32_t)g * 32 + warp_off, o32);
                }
            } else {
                corr = 0.f;
            }

            float sum = 0.f;
            #pragma unroll
            for (int ch = 0; ch < 4; ch++) {
                uint32_t ph[32], pl[32];
                #pragma unroll
                for (int j = 0; j < 32; j++) {
                    float p = fast_exp2(s[ch * 32 + j] - mx);
                    sum += p;
                    float hp = tf32_rn(p);
                    ph[j] = __float_as_uint(hp);
                    pl[j] = __float_as_uint(tf32_rn(p - hp));
                }
                sttm32(tmem + 128 + (uint32_t)ch * 32 + warp_off, ph);
                sttm32(tmem + 256 + (uint32_t)ch * 32 + warp_off, pl);
            }
            asm volatile("tcgen05.wait::st.sync.aligned;" ::: "memory");
            asm volatile("tcgen05.fence::before_thread_sync;" ::: "memory");

            l_run = l_run * corr + sum;
            m_run = mx;
        }
        __syncthreads();

        // ---- PV MMA (TS: A = P in TMEM, B = V^T subtiles) -> O (accumulate) ----
        if (tid == 0) {
            asm volatile("tcgen05.fence::after_thread_sync;" ::: "memory");
            uint64_t vh[4], vl[4];
            #pragma unroll
            for (int vs = 0; vs < 4; vs++) {
                vh[vs] = mk_desc(sb + AS_V + (uint32_t)vs * 8192);
                vl[vs] = mk_desc(sb + AS_V + 32768 + (uint32_t)vs * 8192);
            }
            bool first = true;
            #pragma unroll
            for (int vs = 0; vs < 4; vs++) {
                #pragma unroll
                for (int ks = 0; ks < 4; ks++) {
                    int kk = vs * 4 + ks;
                    uint32_t a_h = tmem + 128 + (uint32_t)kk * 8;
                    uint32_t a_l = tmem + 256 + (uint32_t)kk * 8;
                    uint64_t b_h = vh[vs] + ks * 2, b_l = vl[vs] + ks * 2;
                    uint32_t en0 = (first && i == 0) ? 0u : 1u;
                    mma_tf32_ts(tmem + 384, a_h, b_h, IDPV, en0); first = false;
                    mma_tf32_ts(tmem + 384, a_h, b_l, IDPV, 1u);
                    mma_tf32_ts(tmem + 384, a_l, b_h, IDPV, 1u);
                }
            }
            asm volatile(
                "tcgen05.commit.cta_group::1.mbarrier::arrive::one.shared::cluster.b64 [%0];"
                :: "r"(sb + AS_MPV) : "memory");
        }
    }

    // ---- epilogue ----
    mbar_wait(sb + AS_MPV, qb & 1);
    asm volatile("tcgen05.fence::after_thread_sync;" ::: "memory");
    if (tid < 128) {
        int row = tid;
        float inv_l = 1.0f / l_run;
        float* orow = O + (((size_t)(b * Sc + qb * 128 + row)) * NHc + h) * HDc;
        #pragma unroll
        for (int g = 0; g < 2; g++) {
            uint32_t o32[32];
            ldtm32(o32, tmem + 384 + (uint32_t)g * 32);
            asm volatile("tcgen05.wait::ld.sync.aligned;" ::: "memory");
            #pragma unroll
            for (int j = 0; j < 32; j += 4) {
                float4 v;
                v.x = __uint_as_float(o32[j + 0]) * inv_l;
                v.y = __uint_as_float(o32[j + 1]) * inv_l;
                v.z = __uint_as_float(o32[j + 2]) * inv_l;
                v.w = __uint_as_float(o32[j + 3]) * inv_l;
                *(float4*)(orow + g * 32 + j) = v;
            }
        }
    }
    __syncthreads();
    if (tid < 32) {
        asm volatile("tcgen05.dealloc.cta_group::1.sync.aligned.b32 %0, %1;"
                     :: "r"(tmem), "r"(512u));
    }
#else
    // fp32 fallback (compiles on plain sm_103; GB300 selects the sm_103a cubin)
    float* Ks = (float*)(sm);               // 128 keys x 64
    float* Vs = (float*)(sm + 128 * 64 * 4);
    int row = tid & 127;
    int qi = qb * 128 + row;
    float q[HDc], o[HDc];
    float m = -1e30f, l = 0.f;
    if (tid < 128) {
        #pragma unroll
        for (int d = 0; d < HDc; d++) {
            q[d] = Q[(((size_t)(b * Sc + qi)) * NHc + h) * HDc + d] * SCALE;
            o[d] = 0.f;
        }
    }
    for (int kt = 0; kt <= qb; kt++) {
        int kbase = kt * 128;
        __syncthreads();
        for (int idx = tid; idx < 128 * 16; idx += ATT_THREADS) {
            int r = idx >> 4, c4 = idx & 15;
            ((float4*)Ks)[idx] = *(const float4*)(Kg + (((size_t)(b * Sc + kbase + r)) * NKVc + kh) * HDc + c4 * 4);
        }
        for (int idx = tid; idx < 128 * 16; idx += ATT_THREADS) {
            int d = idx >> 5, c4 = idx & 31;
            float4 v = *(const float4*)(VT + ((size_t)(b * NKVc + kh) * HDc + d) * Sc + kbase + c4 * 4);
            Vs[(c4 * 4 + 0) * 64 + d] = v.x;
            Vs[(c4 * 4 + 1) * 64 + d] = v.y;
            Vs[(c4 * 4 + 2) * 64 + d] = v.z;
            Vs[(c4 * 4 + 3) * 64 + d] = v.w;
        }
        __syncthreads();
        if (tid < 128) {
            int kmax = (kt == qb) ? (row + 1) : 128;
            for (int c = 0; c < kmax; c++) {
                float s = 0.f;
                #pragma unroll
                for (int d = 0; d < HDc; d++) s = fmaf(q[d], Ks[c * 64 + d], s);
                float mn = fmaxf(m, s);
                float cf = fast_exp2(m - mn);
                float p  = fast_exp2(s - mn);
                l = l * cf + p;
                #pragma unroll
                for (int d = 0; d < HDc; d++)
                    o[d] = o[d] * cf + p * Vs[c * 64 + d];
                m = mn;
            }
        }
    }
    if (tid < 128) {
        float inv_l = 1.0f / l;
        #pragma unroll
        for (int d = 0; d < HDc; d++)
            O[(((size_t)(b * Sc + qi)) * NHc + h) * HDc + d] = o[d] * inv_l;
    }
#endif
}

// ---------------------------------------------------------------------------
// launch
// ---------------------------------------------------------------------------
extern "C" void kernel_launch(void* const* d_in, const int* in_sizes, int n_in,
                              void* d_out, int out_size) {
    (void)in_sizes; (void)n_in; (void)out_size;
    const float* x   = (const float*)d_in[0];
    const int*   pos = (const int*)  d_in[1];
    const float* Wq  = (const float*)d_in[2];
    const float* bq  = (const float*)d_in[3];
    const float* Wk  = (const float*)d_in[4];
    const float* bk  = (const float*)d_in[5];
    const float* Wv  = (const float*)d_in[6];
    const float* bv  = (const float*)d_in[7];
    const float* Wo  = (const float*)d_in[8];
    float* out = (float*)d_out;

    float *q, *k, *v, *vt, *att, *cs, *sn;
    float *wqh, *wql, *wkh, *wkl, *wvh, *wvl, *woh, *wol;
    cudaGetSymbolAddress((void**)&q,   g_q);
    cudaGetSymbolAddress((void**)&k,   g_k);
    cudaGetSymbolAddress((void**)&v,   g_v);
    cudaGetSymbolAddress((void**)&vt,  g_vt);
    cudaGetSymbolAddress((void**)&att, g_att);
    cudaGetSymbolAddress((void**)&cs,  g_cos);
    cudaGetSymbolAddress((void**)&sn,  g_sin);
    cudaGetSymbolAddress((void**)&wqh, g_wqh);
    cudaGetSymbolAddress((void**)&wql, g_wql);
    cudaGetSymbolAddress((void**)&wkh, g_wkh);
    cudaGetSymbolAddress((void**)&wkl, g_wkl);
    cudaGetSymbolAddress((void**)&wvh, g_wvh);
    cudaGetSymbolAddress((void**)&wvl, g_wvl);
    cudaGetSymbolAddress((void**)&woh, g_woh);
    cudaGetSymbolAddress((void**)&wol, g_wol);

    cudaFuncSetAttribute(tc_gemm, cudaFuncAttributeMaxDynamicSharedMemorySize, SM_GTOTAL);
    cudaFuncSetAttribute(attn_tc, cudaFuncAttributeMaxDynamicSharedMemorySize, AS_TOTAL);

    // 0) weight transpose + tf32 split
    dim3 tb(32, 8);
    wconv_kernel<<<dim3(2048 / 32, 2048 / 32), tb>>>(Wq, wqh, wql, 2048, 2048);
    wconv_kernel<<<dim3(512  / 32, 2048 / 32), tb>>>(Wk, wkh, wkl, 2048, 512);
    wconv_kernel<<<dim3(512  / 32, 2048 / 32), tb>>>(Wv, wvh, wvl, 2048, 512);
    wconv_kernel<<<dim3(2048 / 32, 2048 / 32), tb>>>(Wo, woh, wol, 2048, 2048);

    // 1) rotary tables
    cossin_kernel<<<(Bc * Sc * HDc + 255) / 256, 256>>>(pos, cs, sn);

    // 2) QKV projections
    tc_gemm<<<dim3(2048 / 128, MQ / 128), GEMM_THREADS, SM_GTOTAL>>>(x, wqh, wql, bq, q, 2048, Hc);
    tc_gemm<<<dim3(512  / 128, MQ / 128), GEMM_THREADS, SM_GTOTAL>>>(x, wkh, wkl, bk, k, 512,  Hc);
    tc_gemm<<<dim3(512  / 128, MQ / 128), GEMM_THREADS, SM_GTOTAL>>>(x, wvh, wvl, bv, v, 512,  Hc);

    // 3) RoPE on q and k; transpose v
    rope_kernel<<<(Bc * Sc * NHc * 32 + 255) / 256, 256>>>(q, cs, sn, NHc, Bc * Sc * NHc * 32);
    rope_kernel<<<(Bc * Sc * NKVc * 32 + 255) / 256, 256>>>(k, cs, sn, NKVc, Bc * Sc * NKVc * 32);
    vtrans_kernel<<<dim3(Sc / 32, HDc / 32, Bc * NKVc), tb>>>(v, vt);

    // 4) tensor-core causal GQA attention
    attn_tc<<<dim3(16, NHc, Bc), ATT_THREADS, AS_TOTAL>>>(q, k, vt, att);

    // 5) output projection
    tc_gemm<<<dim3(2048 / 128, MQ / 128), GEMM_THREADS, SM_GTOTAL>>>(att, woh, wol, nullptr, out, 2048, Hc);
}

// round 5
// speedup vs baseline: 5.0157x; 2.2003x over previous
#include <cuda_runtime.h>
#include <cuda_fp16.h>
#include <math.h>
#include <stdint.h>

// Problem constants
#define Bc   2
#define Sc   2048
#define Hc   2048
#define NHc  32
#define NKVc 8
#define HDc  64
#define MQ   (Bc * Sc)          // 4096 rows

#if defined(__CUDA_ARCH__) && defined(__CUDA_ARCH_FEAT_SM103_ALL)
#define HAS_TCGEN05 1
#else
#define HAS_TCGEN05 0
#endif

// ---------------------------------------------------------------------------
// Scratch (device globals)
// ---------------------------------------------------------------------------
__device__ float  g_q  [(size_t)MQ * NHc  * HDc];       // fp32 after GEMM (pre-rope)
__device__ float  g_k  [(size_t)MQ * NKVc * HDc];
__device__ float  g_v  [(size_t)MQ * NKVc * HDc];
__device__ float  g_cos[(size_t)MQ * HDc];
__device__ float  g_sin[(size_t)MQ * HDc];
// fp16 hi/lo split operands
__device__ __half g_xh [(size_t)MQ * Hc],        g_xl [(size_t)MQ * Hc];
__device__ __half g_qh [(size_t)MQ * NHc * HDc], g_ql [(size_t)MQ * NHc * HDc];
__device__ __half g_kh [(size_t)MQ * NKVc * HDc], g_kl [(size_t)MQ * NKVc * HDc];
__device__ __half g_vth[(size_t)Bc * NKVc * HDc * Sc], g_vtl[(size_t)Bc * NKVc * HDc * Sc];
__device__ __half g_ath[(size_t)MQ * Hc],        g_atl[(size_t)MQ * Hc];
// transposed + fp16-split weights: [N, K] row-major
__device__ __half g_wqh[(size_t)2048 * 2048], g_wql[(size_t)2048 * 2048];
__device__ __half g_wkh[(size_t)512  * 2048], g_wkl[(size_t)512  * 2048];
__device__ __half g_wvh[(size_t)512  * 2048], g_wvl[(size_t)512  * 2048];
__device__ __half g_woh[(size_t)2048 * 2048], g_wol[(size_t)2048 * 2048];

// ---------------------------------------------------------------------------
// helpers
// ---------------------------------------------------------------------------
__device__ __forceinline__ uint32_t smem_u32(const void* p) {
    uint32_t a;
    asm("{ .reg .u64 t; cvta.to.shared.u64 t, %1; cvt.u32.u64 %0, t; }" : "=r"(a) : "l"(p));
    return a;
}
__device__ __forceinline__ float fast_exp2(float x) {
    float y;
    asm("ex2.approx.ftz.f32 %0, %1;" : "=f"(y) : "f"(x));
    return y;
}
__device__ __forceinline__ void split_h(float x, __half& h, __half& l) {
    h = __float2half_rn(x);
    l = __float2half_rn(x - __half2float(h));
}

#if HAS_TCGEN05
__device__ __forceinline__ uint64_t mk_desc(uint32_t addr) {
    // SW128, version=1 (Blackwell), SBO=64, LBO=1
    return ((uint64_t)2 << 61) | ((uint64_t)1 << 46) | ((uint64_t)64 << 32) |
           ((uint64_t)1 << 16) | ((uint64_t)((addr >> 4) & 0x3FFF));
}
__device__ __forceinline__ void mma_f16(uint32_t d, uint64_t ad, uint64_t bd,
                                        uint32_t idesc, uint32_t en) {
    asm volatile(
        "{\n\t.reg .pred p;\n\t"
        "setp.ne.u32 p, %4, 0;\n\t"
        "tcgen05.mma.cta_group::1.kind::f16 [%0], %1, %2, %3, {%5, %5, %5, %5}, p;\n\t}"
        :: "r"(d), "l"(ad), "l"(bd), "r"(idesc), "r"(en), "r"(0u) : "memory");
}
__device__ __forceinline__ void mma_f16_ts(uint32_t d, uint32_t a, uint64_t bd,
                                           uint32_t idesc, uint32_t en) {
    asm volatile(
        "{\n\t.reg .pred p;\n\t"
        "setp.ne.u32 p, %4, 0;\n\t"
        "tcgen05.mma.cta_group::1.kind::f16 [%0], [%1], %2, %3, {%5, %5, %5, %5}, p;\n\t}"
        :: "r"(d), "r"(a), "l"(bd), "r"(idesc), "r"(en), "r"(0u) : "memory");
}
__device__ __forceinline__ void mbar_wait(uint32_t m, uint32_t par) {
    asm volatile(
        "{\n\t.reg .pred P;\n\t"
        "WL%=:\n\t"
        "mbarrier.try_wait.parity.acquire.cta.shared::cta.b64 P, [%0], %1, 0x989680;\n\t"
        "@!P bra WL%=;\n\t}"
        :: "r"(m), "r"(par) : "memory");
}
__device__ __forceinline__ void ldtm32(uint32_t* r, uint32_t addr) {
    asm volatile(
        "tcgen05.ld.sync.aligned.32x32b.x32.b32 "
        "{%0, %1, %2, %3, %4, %5, %6, %7, "
        " %8, %9, %10, %11, %12, %13, %14, %15, "
        " %16, %17, %18, %19, %20, %21, %22, %23, "
        " %24, %25, %26, %27, %28, %29, %30, %31}, [%32];"
        : "=r"(r[0]),  "=r"(r[1]),  "=r"(r[2]),  "=r"(r[3]),
          "=r"(r[4]),  "=r"(r[5]),  "=r"(r[6]),  "=r"(r[7]),
          "=r"(r[8]),  "=r"(r[9]),  "=r"(r[10]), "=r"(r[11]),
          "=r"(r[12]), "=r"(r[13]), "=r"(r[14]), "=r"(r[15]),
          "=r"(r[16]), "=r"(r[17]), "=r"(r[18]), "=r"(r[19]),
          "=r"(r[20]), "=r"(r[21]), "=r"(r[22]), "=r"(r[23]),
          "=r"(r[24]), "=r"(r[25]), "=r"(r[26]), "=r"(r[27]),
          "=r"(r[28]), "=r"(r[29]), "=r"(r[30]), "=r"(r[31])
        : "r"(addr));
}
__device__ __forceinline__ void sttm32(uint32_t addr, const uint32_t* r) {
    asm volatile(
        "tcgen05.st.sync.aligned.32x32b.x32.b32 [%0], "
        "{%1, %2, %3, %4, %5, %6, %7, %8, "
        " %9, %10, %11, %12, %13, %14, %15, %16, "
        " %17, %18, %19, %20, %21, %22, %23, %24, "
        " %25, %26, %27, %28, %29, %30, %31, %32};"
        :: "r"(addr),
           "r"(r[0]),  "r"(r[1]),  "r"(r[2]),  "r"(r[3]),
           "r"(r[4]),  "r"(r[5]),  "r"(r[6]),  "r"(r[7]),
           "r"(r[8]),  "r"(r[9]),  "r"(r[10]), "r"(r[11]),
           "r"(r[12]), "r"(r[13]), "r"(r[14]), "r"(r[15]),
           "r"(r[16]), "r"(r[17]), "r"(r[18]), "r"(r[19]),
           "r"(r[20]), "r"(r[21]), "r"(r[22]), "r"(r[23]),
           "r"(r[24]), "r"(r[25]), "r"(r[26]), "r"(r[27]),
           "r"(r[28]), "r"(r[29]), "r"(r[30]), "r"(r[31])
        : "memory");
}
__device__ __forceinline__ void sttm16(uint32_t addr, const uint32_t* r) {
    asm volatile(
        "tcgen05.st.sync.aligned.32x32b.x16.b32 [%0], "
        "{%1, %2, %3, %4, %5, %6, %7, %8, "
        " %9, %10, %11, %12, %13, %14, %15, %16};"
        :: "r"(addr),
           "r"(r[0]),  "r"(r[1]),  "r"(r[2]),  "r"(r[3]),
           "r"(r[4]),  "r"(r[5]),  "r"(r[6]),  "r"(r[7]),
           "r"(r[8]),  "r"(r[9]),  "r"(r[10]), "r"(r[11]),
           "r"(r[12]), "r"(r[13]), "r"(r[14]), "r"(r[15])
        : "memory");
}
#endif

// ---------------------------------------------------------------------------
// mRoPE cos/sin table
// ---------------------------------------------------------------------------
__global__ void cossin_kernel(const int* __restrict__ pos,
                              float* __restrict__ cosb,
                              float* __restrict__ sinb) {
    int idx = blockIdx.x * blockDim.x + threadIdx.x;
    if (idx >= Bc * Sc * HDc) return;
    int d  = idx & 63;
    int bs = idx >> 6;
    int i  = d & 31;
    int sec = (i < 16) ? 0 : 1;
    float p = (float)pos[sec * (Bc * Sc) + bs];
    float inv_freq = exp2f(-0.6228615177913804f * (float)i);
    float ang = p * inv_freq;
    float s, c;
    sincosf(ang, &s, &c);
    cosb[idx] = c;
    sinb[idx] = s;
}

// ---------------------------------------------------------------------------
// x -> fp16 hi/lo split
// ---------------------------------------------------------------------------
__global__ void xsplit_kernel(const float* __restrict__ X,
                              __half* __restrict__ Xh, __half* __restrict__ Xl,
                              int n4) {
    int idx = blockIdx.x * blockDim.x + threadIdx.x;
    if (idx >= n4) return;
    float4 v = ((const float4*)X)[idx];
    __half h, l;
    split_h(v.x, h, l); Xh[idx*4+0] = h; Xl[idx*4+0] = l;
    split_h(v.y, h, l); Xh[idx*4+1] = h; Xl[idx*4+1] = l;
    split_h(v.z, h, l); Xh[idx*4+2] = h; Xl[idx*4+2] = l;
    split_h(v.w, h, l); Xh[idx*4+3] = h; Xl[idx*4+3] = l;
}

// ---------------------------------------------------------------------------
// RoPE + fp16 split (scale folded in for Q)
// ---------------------------------------------------------------------------
__global__ void rope_split_kernel(const float* __restrict__ X,
                                  const float* __restrict__ cosb,
                                  const float* __restrict__ sinb,
                                  __half* __restrict__ Xh, __half* __restrict__ Xl,
                                  int nheads, float scale, int total_pairs) {
    int idx = blockIdx.x * blockDim.x + threadIdx.x;
    if (idx >= total_pairs) return;
    int d    = idx & 31;
    int rest = idx >> 5;
    int bs   = rest / nheads;
    const float* p  = X + (size_t)rest * HDc;
    const float* cb = cosb + (size_t)bs * HDc;
    const float* sb = sinb + (size_t)bs * HDc;
    float x1 = p[d], x2 = p[d + 32];
    float y1 = (x1 * cb[d]      - x2 * sb[d])      * scale;
    float y2 = (x2 * cb[d + 32] + x1 * sb[d + 32]) * scale;
    __half h, l;
    split_h(y1, h, l);
    Xh[(size_t)rest * HDc + d] = h;  Xl[(size_t)rest * HDc + d] = l;
    split_h(y2, h, l);
    Xh[(size_t)rest * HDc + d + 32] = h;  Xl[(size_t)rest * HDc + d + 32] = l;
}

// ---------------------------------------------------------------------------
// Weight transpose + fp16 hi/lo split: W[K,N] -> Th[N,K], Tl[N,K]
// ---------------------------------------------------------------------------
__global__ void wconv_kernel(const float* __restrict__ W,
                             __half* __restrict__ Th, __half* __restrict__ Tl,
                             int K, int N) {
    __shared__ float t[32][33];
    int n0 = blockIdx.x * 32, k0 = blockIdx.y * 32;
    int c = threadIdx.x, r0 = threadIdx.y;          // block (32,8)
    #pragma unroll
    for (int i = 0; i < 4; i++) {
        int kk = r0 + i * 8;
        t[kk][c] = W[(size_t)(k0 + kk) * N + n0 + c];
    }
    __syncthreads();
    #pragma unroll
    for (int i = 0; i < 4; i++) {
        int nn = r0 + i * 8;
        float v = t[c][nn];
        __half h, l;
        split_h(v, h, l);
        size_t o = (size_t)(n0 + nn) * K + k0 + c;
        Th[o] = h;
        Tl[o] = l;
    }
}

// ---------------------------------------------------------------------------
// V transpose + split: v[b,s,kv,64] fp32 -> vth/vtl[b,kv,64,s] fp16
// ---------------------------------------------------------------------------
__global__ void vtrans_kernel(const float* __restrict__ V,
                              __half* __restrict__ VTh, __half* __restrict__ VTl) {
    __shared__ float t[32][33];
    int s0 = blockIdx.x * 32, d0 = blockIdx.y * 32;
    int bkv = blockIdx.z;
    int b = bkv >> 3, kv = bkv & 7;
    int c = threadIdx.x, r0 = threadIdx.y;   // block (32,8)
    #pragma unroll
    for (int i = 0; i < 4; i++) {
        int ss = r0 + i * 8;
        t[ss][c] = V[(((size_t)(b * Sc + s0 + ss)) * NKVc + kv) * HDc + d0 + c];
    }
    __syncthreads();
    #pragma unroll
    for (int i = 0; i < 4; i++) {
        int dd = r0 + i * 8;
        __half h, l;
        split_h(t[c][dd], h, l);
        size_t o = ((size_t)bkv * HDc + d0 + dd) * Sc + s0 + c;
        VTh[o] = h;
        VTl[o] = l;
    }
}

// ---------------------------------------------------------------------------
// fp16x3 GEMM: C[M,N] = A @ Bt^T, A as (Ah,Al) [M,K], Bt as (Bh,Bl) [N,K]
// 128x128 tile, K chunk 64 (one SW128 row of fp16), double-buffered.
// ---------------------------------------------------------------------------
#define GEMM_THREADS 256
#define SM_TMEMPTR 0
#define SM_MBAR    16
#define SM_TILES   1024
#define GTILE_B    16384            // 128 rows x 128 bytes (64 fp16)
#define GBUF_B     (4 * GTILE_B)    // Ah, Al, Bh, Bl
#define SM_STAGE   (SM_TILES + 2 * GBUF_B)
#define SM_GTOTAL  (SM_STAGE + 128 * 33 * 4)

__global__ __launch_bounds__(GEMM_THREADS, 1)
void tc_gemm(const __half* __restrict__ Ah, const __half* __restrict__ Al,
             const __half* __restrict__ Bh, const __half* __restrict__ Bl,
             const float* __restrict__ bias, float* __restrict__ C,
             int N, int K) {
    extern __shared__ char sm[];
    int tid = threadIdx.x;
    int m0 = blockIdx.y * 128, n0 = blockIdx.x * 128;

#if HAS_TCGEN05
    uint32_t sb = smem_u32(sm);
    if (tid == 0) {
        asm volatile("mbarrier.init.shared.b64 [%0], 1;" :: "r"(sb + SM_MBAR) : "memory");
        asm volatile("mbarrier.init.shared.b64 [%0], 1;" :: "r"(sb + SM_MBAR + 8) : "memory");
    }
    if (tid < 32) {
        asm volatile("tcgen05.alloc.cta_group::1.sync.aligned.shared::cta.b32 [%0], %1;"
                     :: "r"(sb + SM_TMEMPTR), "r"(128u) : "memory");
        asm volatile("tcgen05.relinquish_alloc_permit.cta_group::1.sync.aligned;");
    }
    __syncthreads();
    uint32_t tmem;
    asm volatile("ld.shared.b32 %0, [%1];" : "=r"(tmem) : "r"(sb + SM_TMEMPTR));

    const uint32_t idesc = (1u << 4) | (16u << 17) | (8u << 24);  // f16, N=128, M=128
    const int NC = K >> 6;                                        // 64-wide K chunks

    auto load_tiles = [&](int buf, int k0) {
        char* base = sm + SM_TILES + (size_t)buf * GBUF_B;
        #pragma unroll
        for (int i2 = 0; i2 < 4; i2++) {
            int idx = tid + i2 * 256;
            int r = idx >> 3, c8 = idx & 7;
            uint32_t off = (uint32_t)(r * 128 + c8 * 16);
            off ^= (off >> 3) & 0x70;
            size_t ga = (size_t)(m0 + r) * K + k0 + c8 * 8;
            size_t gb = (size_t)(n0 + r) * K + k0 + c8 * 8;
            *(float4*)(base + off)                 = *(const float4*)(Ah + ga);
            *(float4*)(base + GTILE_B + off)       = *(const float4*)(Al + ga);
            *(float4*)(base + 2 * GTILE_B + off)   = *(const float4*)(Bh + gb);
            *(float4*)(base + 3 * GTILE_B + off)   = *(const float4*)(Bl + gb);
        }
    };

    load_tiles(0, 0);
    int ph0 = 0, ph1 = 0;
    for (int c = 0; c < NC; ++c) {
        int cur = c & 1;
        __syncthreads();
        if (tid == 0) {
            asm volatile("fence.proxy.async.shared::cta;" ::: "memory");
            uint32_t tb = sb + SM_TILES + (uint32_t)cur * GBUF_B;
            uint64_t ahd = mk_desc(tb);
            uint64_t ald = mk_desc(tb + GTILE_B);
            uint64_t bhd = mk_desc(tb + 2 * GTILE_B);
            uint64_t bld = mk_desc(tb + 3 * GTILE_B);
            #pragma unroll
            for (int ks = 0; ks < 4; ++ks) {           // 16 fp16 per step
                uint32_t en0 = (c == 0 && ks == 0) ? 0u : 1u;
                mma_f16(tmem, ahd + ks * 2, bhd + ks * 2, idesc, en0);
                mma_f16(tmem, ahd + ks * 2, bld + ks * 2, idesc, 1u);
                mma_f16(tmem, ald + ks * 2, bhd + ks * 2, idesc, 1u);
            }
            asm volatile(
                "tcgen05.commit.cta_group::1.mbarrier::arrive::one.shared::cluster.b64 [%0];"
                :: "r"(sb + SM_MBAR + (uint32_t)cur * 8) : "memory");
        }
        if (c + 1 < NC) {
            int nxt = cur ^ 1;
            if (c >= 1) {
                mbar_wait(sb + SM_MBAR + (uint32_t)nxt * 8, nxt ? ph1 : ph0);
                if (nxt) ph1 ^= 1; else ph0 ^= 1;
            }
            load_tiles(nxt, (c + 1) << 6);
        }
    }
    {
        int last = (NC - 1) & 1;
        mbar_wait(sb + SM_MBAR + (uint32_t)last * 8, last ? ph1 : ph0);
    }
    asm volatile("tcgen05.fence::after_thread_sync;" ::: "memory");
    __syncthreads();

    float* stage = (float*)(sm + SM_STAGE);
    int wid = tid >> 5, lid = tid & 31;
    for (int g = 0; g < 4; ++g) {
        if (tid < 128) {
            uint32_t d[32];
            ldtm32(d, tmem + (uint32_t)g * 32);
            asm volatile("tcgen05.wait::ld.sync.aligned;" ::: "memory");
            int row = wid * 32 + lid;
            #pragma unroll
            for (int j = 0; j < 32; ++j)
                stage[row * 33 + j] = __uint_as_float(d[j]);
        }
        __syncthreads();
        #pragma unroll
        for (int i = 0; i < 4; ++i) {
            int rr = (tid >> 3) + i * 32;
            int c4 = tid & 7;
            float x0 = stage[rr * 33 + c4 * 4 + 0];
            float x1 = stage[rr * 33 + c4 * 4 + 1];
            float x2 = stage[rr * 33 + c4 * 4 + 2];
            float x3 = stage[rr * 33 + c4 * 4 + 3];
            int n = n0 + g * 32 + c4 * 4;
            if (bias) {
                x0 += bias[n + 0]; x1 += bias[n + 1];
                x2 += bias[n + 2]; x3 += bias[n + 3];
            }
            *(float4*)(C + (size_t)(m0 + rr) * N + n) = make_float4(x0, x1, x2, x3);
        }
        __syncthreads();
    }

    if (tid < 32) {
        asm volatile("tcgen05.dealloc.cta_group::1.sync.aligned.b32 %0, %1;"
                     :: "r"(tmem), "r"(128u));
    }
#else
    // FFMA fallback (plain sm_103 pass; GB300 loads the sm_103a cubin)
    float (*As)[128] = (float (*)[128])(sm);
    float (*Bs)[128] = (float (*)[128])(sm + 8192);
    int tcol = tid & 15;
    int trow = tid >> 4;
    float acc[8][8];
    #pragma unroll
    for (int i = 0; i < 8; i++)
        #pragma unroll
        for (int j = 0; j < 8; j++) acc[i][j] = 0.f;
    for (int k0 = 0; k0 < K; k0 += 16) {
        for (int idx = tid; idx < 512; idx += 256) {
            int r  = idx >> 2;
            int c4 = idx & 3;
            #pragma unroll
            for (int e = 0; e < 4; e++) {
                int kk = c4 * 4 + e;
                size_t ga = (size_t)(m0 + r) * K + k0 + kk;
                size_t gb = (size_t)(n0 + r) * K + k0 + kk;
                As[kk][r] = __half2float(Ah[ga]) + __half2float(Al[ga]);
                Bs[kk][r] = __half2float(Bh[gb]) + __half2float(Bl[gb]);
            }
        }
        __syncthreads();
        #pragma unroll
        for (int kk = 0; kk < 16; kk++) {
            float ra[8], rb[8];
            *(float4*)&ra[0] = *(const float4*)&As[kk][trow * 8];
            *(float4*)&ra[4] = *(const float4*)&As[kk][trow * 8 + 4];
            *(float4*)&rb[0] = *(const float4*)&Bs[kk][tcol * 8];
            *(float4*)&rb[4] = *(const float4*)&Bs[kk][tcol * 8 + 4];
            #pragma unroll
            for (int i = 0; i < 8; i++)
                #pragma unroll
                for (int j = 0; j < 8; j++)
                    acc[i][j] = fmaf(ra[i], rb[j], acc[i][j]);
        }
        __syncthreads();
    }
    #pragma unroll
    for (int i = 0; i < 8; i++) {
        int m = m0 + trow * 8 + i;
        #pragma unroll
        for (int jj = 0; jj < 8; jj++) {
            int n = n0 + tcol * 8 + jj;
            float v = acc[i][jj];
            if (bias) v += bias[n];
            C[(size_t)m * N + n] = v;
        }
    }
#endif
}

// ---------------------------------------------------------------------------
// Tensor-core causal GQA attention (fp16x3)
//  CTA = (128 q rows, one head). Double-buffered K/V; threads 128-255 load
//  tile i+1 while threads 0-127 run softmax of tile i.
//  TMEM: S @0 (128 f32) | Ph @128 (64 f16x2) | Pl @192 (64) | O @256 (64 f32)
// ---------------------------------------------------------------------------
#define ATT_THREADS 256
#define AS_TMEM   0
#define AS_MQK    16
#define AS_MPV    24
#define AS_Q      1024
#define AS_KV     (AS_Q + 32768)
#define KVBUF_B   65536              // Kh 16K | Kl 16K | Vh 2x8K | Vl 2x8K
#define AS_TOTAL  (AS_KV + 2 * KVBUF_B + 64)

__global__ __launch_bounds__(ATT_THREADS, 1)
void attn_tc(const __half* __restrict__ QH, const __half* __restrict__ QL,
             const __half* __restrict__ KH, const __half* __restrict__ KL,
             const __half* __restrict__ VTH, const __half* __restrict__ VTL,
             __half* __restrict__ ATH, __half* __restrict__ ATL) {
    extern __shared__ char sm[];
    int tid = threadIdx.x;
    int qb = 15 - (int)blockIdx.x;          // big tiles first
    int hd = blockIdx.y, b = blockIdx.z;
    int khead = hd >> 2;

#if HAS_TCGEN05
    uint32_t sb = smem_u32(sm);
    if (tid == 0) {
        asm volatile("mbarrier.init.shared.b64 [%0], 1;" :: "r"(sb + AS_MQK) : "memory");
        asm volatile("mbarrier.init.shared.b64 [%0], 1;" :: "r"(sb + AS_MPV) : "memory");
    }
    if (tid < 32) {
        asm volatile("tcgen05.alloc.cta_group::1.sync.aligned.shared::cta.b32 [%0], %1;"
                     :: "r"(sb + AS_TMEM), "r"(512u) : "memory");
        asm volatile("tcgen05.relinquish_alloc_permit.cta_group::1.sync.aligned;");
    }
    __syncthreads();
    uint32_t tmem;
    asm volatile("ld.shared.b32 %0, [%1];" : "=r"(tmem) : "r"(sb + AS_TMEM));

    const uint32_t IDQK = (1u << 4) | (16u << 17) | (8u << 24);  // f16 M128 N128
    const uint32_t IDPV = (1u << 4) | (8u  << 17) | (8u << 24);  // f16 M128 N64

    // ---- Q tile (once): pure copies of pre-split fp16 ----
    #pragma unroll
    for (int i2 = 0; i2 < 4; i2++) {
        int idx = tid + i2 * 256;
        int r = idx >> 3, c8 = idx & 7;
        uint32_t off = (uint32_t)(r * 128 + c8 * 16);
        off ^= (off >> 3) & 0x70;
        size_t go = (((size_t)(b * Sc + qb * 128 + r)) * NHc + hd) * HDc + c8 * 8;
        *(float4*)(sm + AS_Q + off)         = *(const float4*)(QH + go);
        *(float4*)(sm + AS_Q + 16384 + off) = *(const float4*)(QL + go);
    }

    // K/V tile loader (lt in [0,nt))
    auto load_kv = [&](int buf, int kbase, int lt, int nt) {
        char* base = sm + AS_KV + (size_t)buf * KVBUF_B;
        for (int idx = lt; idx < 1024; idx += nt) {          // K: 128 rows x 64 fp16
            int r = idx >> 3, c8 = idx & 7;
            uint32_t off = (uint32_t)(r * 128 + c8 * 16);
            off ^= (off >> 3) & 0x70;
            size_t go = (((size_t)(b * Sc + kbase + r)) * NKVc + khead) * HDc + c8 * 8;
            *(float4*)(base + off)         = *(const float4*)(KH + go);
            *(float4*)(base + 16384 + off) = *(const float4*)(KL + go);
        }
        for (int idx = lt; idx < 1024; idx += nt) {          // V^T: 64 d-rows x 128 keys
            int d = idx >> 4, c8 = idx & 15;
            int sub = c8 >> 3;
            uint32_t off = (uint32_t)(d * 128 + (c8 & 7) * 16);
            off ^= (off >> 3) & 0x70;
            size_t go = ((size_t)(b * NKVc + khead) * HDc + d) * Sc + kbase + c8 * 8;
            *(float4*)(base + 32768 + sub * 8192 + off) = *(const float4*)(VTH + go);
            *(float4*)(base + 49152 + sub * 8192 + off) = *(const float4*)(VTL + go);
        }
    };

    load_kv(0, 0, tid, 256);
    __syncthreads();

    float m_run = -1e30f, l_run = 0.f;
    uint32_t warp_off = ((uint32_t)(tid >> 5)) << 21;

    for (int i = 0; i <= qb; i++) {
        int cur = i & 1;
        uint32_t kvb = sb + AS_KV + (uint32_t)cur * KVBUF_B;

        // ---- QK MMA ----
        if (tid == 0) {
            asm volatile("fence.proxy.async.shared::cta;" ::: "memory");
            uint64_t qhd = mk_desc(sb + AS_Q);
            uint64_t qld = mk_desc(sb + AS_Q + 16384);
            uint64_t khd = mk_desc(kvb);
            uint64_t kld = mk_desc(kvb + 16384);
            #pragma unroll
            for (int ks = 0; ks < 4; ks++) {
                mma_f16(tmem, qhd + ks * 2, khd + ks * 2, IDQK, ks == 0 ? 0u : 1u);
                mma_f16(tmem, qhd + ks * 2, kld + ks * 2, IDQK, 1u);
                mma_f16(tmem, qld + ks * 2, khd + ks * 2, IDQK, 1u);
            }
            asm volatile(
                "tcgen05.commit.cta_group::1.mbarrier::arrive::one.shared::cluster.b64 [%0];"
                :: "r"(sb + AS_MQK) : "memory");
        }

        if (tid >= 128) {
            // ---- loader half: prefetch tile i+1 while softmax runs ----
            if (i + 1 <= qb) {
                if (i >= 1) mbar_wait(sb + AS_MPV, (i - 1) & 1);
                load_kv(cur ^ 1, (i + 1) * 128, tid - 128, 128);
            }
        } else {
            // ---- softmax half ----
            int row = tid;
            mbar_wait(sb + AS_MQK, i & 1);
            if (i > 0) mbar_wait(sb + AS_MPV, (i - 1) & 1);
            asm volatile("tcgen05.fence::after_thread_sync;" ::: "memory");

            // pass 1: row max
            float mx = m_run;
            #pragma unroll
            for (int ch = 0; ch < 4; ch++) {
                uint32_t r32[32];
                ldtm32(r32, tmem + (uint32_t)ch * 32);
                asm volatile("tcgen05.wait::ld.sync.aligned;" ::: "memory");
                #pragma unroll
                for (int j = 0; j < 32; j++) {
                    int key = ch * 32 + j;
                    float sv = (i == qb && key > row) ? -1e30f : __uint_as_float(r32[j]);
                    mx = fmaxf(mx, sv);
                }
            }
            float corr = fast_exp2(m_run - mx);
            if (i > 0) {
                #pragma unroll
                for (int g = 0; g < 2; g++) {
                    uint32_t o32[32];
                    ldtm32(o32, tmem + 256 + (uint32_t)g * 32);
                    asm volatile("tcgen05.wait::ld.sync.aligned;" ::: "memory");
                    #pragma unroll
                    for (int j = 0; j < 32; j++)
                        o32[j] = __float_as_uint(__uint_as_float(o32[j]) * corr);
                    sttm32(tmem + 256 + (uint32_t)g * 32 + warp_off, o32);
                }
            } else {
                corr = 0.f;
            }

            // pass 2: P = exp2(s - mx), split fp16 hi/lo, pack pairs, STTM
            float sum = 0.f;
            #pragma unroll
            for (int ch = 0; ch < 4; ch++) {
                uint32_t r32[32];
                ldtm32(r32, tmem + (uint32_t)ch * 32);
                asm volatile("tcgen05.wait::ld.sync.aligned;" ::: "memory");
                uint32_t phw[16], plw[16];
                #pragma unroll
                for (int j = 0; j < 16; j++) {
                    int k0 = ch * 32 + j * 2;
                    float s0 = (i == qb && k0 > row)     ? -1e30f : __uint_as_float(r32[j*2]);
                    float s1 = (i == qb && k0 + 1 > row) ? -1e30f : __uint_as_float(r32[j*2+1]);
                    float p0 = fast_exp2(s0 - mx);
                    float p1 = fast_exp2(s1 - mx);
                    sum += p0 + p1;
                    __half h0 = __float2half_rn(p0);
                    __half h1 = __float2half_rn(p1);
                    float l0 = p0 - __half2float(h0);
                    float l1 = p1 - __half2float(h1);
                    __half2 hp = __halves2half2(h0, h1);
                    __half2 lp = __floats2half2_rn(l0, l1);
                    phw[j] = *(uint32_t*)&hp;
                    plw[j] = *(uint32_t*)&lp;
                }
                sttm16(tmem + 128 + (uint32_t)ch * 16 + warp_off, phw);
                sttm16(tmem + 192 + (uint32_t)ch * 16 + warp_off, plw);
            }
            asm volatile("tcgen05.wait::st.sync.aligned;" ::: "memory");
            asm volatile("tcgen05.fence::before_thread_sync;" ::: "memory");

            l_run = l_run * corr + sum;
            m_run = mx;
        }
        __syncthreads();

        // ---- PV MMA (TS: A = P fp16x2 in TMEM, B = V^T subtiles) ----
        if (tid == 0) {
            asm volatile("tcgen05.fence::after_thread_sync;" ::: "memory");
            #pragma unroll
            for (int kk = 0; kk < 8; kk++) {             // 16 keys per step
                int sub = kk >> 2, ks = kk & 3;
                uint64_t vh = mk_desc(kvb + 32768 + (uint32_t)sub * 8192) + ks * 2;
                uint64_t vl = mk_desc(kvb + 49152 + (uint32_t)sub * 8192) + ks * 2;
                uint32_t ah = tmem + 128 + (uint32_t)kk * 8;
                uint32_t al = tmem + 192 + (uint32_t)kk * 8;
                mma_f16_ts(tmem + 256, ah, vh, IDPV, (i == 0 && kk == 0) ? 0u : 1u);
                mma_f16_ts(tmem + 256, ah, vl, IDPV, 1u);
                mma_f16_ts(tmem + 256, al, vh, IDPV, 1u);
            }
            asm volatile(
                "tcgen05.commit.cta_group::1.mbarrier::arrive::one.shared::cluster.b64 [%0];"
                :: "r"(sb + AS_MPV) : "memory");
        }
    }

    // ---- epilogue: O/l -> fp16 hi/lo att ----
    mbar_wait(sb + AS_MPV, qb & 1);
    asm volatile("tcgen05.fence::after_thread_sync;" ::: "memory");
    if (tid < 128) {
        int row = tid;
        float inv_l = 1.0f / l_run;
        size_t obase = ((size_t)(b * Sc + qb * 128 + row)) * (NHc * HDc) + (size_t)hd * HDc;
        #pragma unroll
        for (int g = 0; g < 2; g++) {
            uint32_t o32[32];
            ldtm32(o32, tmem + 256 + (uint32_t)g * 32);
            asm volatile("tcgen05.wait::ld.sync.aligned;" ::: "memory");
            #pragma unroll
            for (int j = 0; j < 32; j += 2) {
                float v0 = __uint_as_float(o32[j])     * inv_l;
                float v1 = __uint_as_float(o32[j + 1]) * inv_l;
                __half h0, l0, h1, l1;
                split_h(v0, h0, l0);
                split_h(v1, h1, l1);
                *(__half2*)(ATH + obase + g * 32 + j) = __halves2half2(h0, h1);
                *(__half2*)(ATL + obase + g * 32 + j) = __halves2half2(l0, l1);
            }
        }
    }
    __syncthreads();
    if (tid < 32) {
        asm volatile("tcgen05.dealloc.cta_group::1.sync.aligned.b32 %0, %1;"
                     :: "r"(tmem), "r"(512u));
    }
#else
    // fp32 flash fallback (plain sm_103 pass only)
    float* Ks = (float*)(sm);
    float* Vs = (float*)(sm + 128 * 64 * 4);
    int row = tid & 127;
    int qi = qb * 128 + row;
    float q[HDc], o[HDc];
    float m = -1e30f, l = 0.f;
    if (tid < 128) {
        #pragma unroll
        for (int d = 0; d < HDc; d++) {
            size_t go = (((size_t)(b * Sc + qi)) * NHc + hd) * HDc + d;
            q[d] = __half2float(QH[go]) + __half2float(QL[go]);
            o[d] = 0.f;
        }
    }
    for (int kt = 0; kt <= qb; kt++) {
        int kbase = kt * 128;
        __syncthreads();
        for (int idx = tid; idx < 128 * 64; idx += ATT_THREADS) {
            int r = idx >> 6, d = idx & 63;
            size_t go = (((size_t)(b * Sc + kbase + r)) * NKVc + khead) * HDc + d;
            Ks[r * 64 + d] = __half2float(KH[go]) + __half2float(KL[go]);
            size_t gv = ((size_t)(b * NKVc + khead) * HDc + d) * Sc + kbase + r;
            Vs[r * 64 + d] = __half2float(VTH[gv]) + __half2float(VTL[gv]);
        }
        __syncthreads();
        if (tid < 128) {
            int kmax = (kt == qb) ? (row + 1) : 128;
            for (int c = 0; c < kmax; c++) {
                float s = 0.f;
                #pragma unroll
                for (int d = 0; d < HDc; d++) s = fmaf(q[d], Ks[c * 64 + d], s);
                float mn = fmaxf(m, s);
                float cf = fast_exp2(m - mn);
                float p  = fast_exp2(s - mn);
                l = l * cf + p;
                #pragma unroll
                for (int d = 0; d < HDc; d++)
                    o[d] = o[d] * cf + p * Vs[c * 64 + d];
                m = mn;
            }
        }
    }
    if (tid < 128) {
        float inv_l = 1.0f / l;
        #pragma unroll
        for (int d = 0; d < HDc; d++) {
            float v = o[d] * inv_l;
            __half h, lo;
            split_h(v, h, lo);
            size_t go = (((size_t)(b * Sc + qi)) * NHc + hd) * HDc + d;
            ATH[go] = h;
            ATL[go] = lo;
        }
    }
#endif
}

// ---------------------------------------------------------------------------
// launch
// ---------------------------------------------------------------------------
extern "C" void kernel_launch(void* const* d_in, const int* in_sizes, int n_in,
                              void* d_out, int out_size) {
    (void)in_sizes; (void)n_in; (void)out_size;
    const float* x   = (const float*)d_in[0];
    const int*   pos = (const int*)  d_in[1];
    const float* Wq  = (const float*)d_in[2];
    const float* bq  = (const float*)d_in[3];
    const float* Wk  = (const float*)d_in[4];
    const float* bk  = (const float*)d_in[5];
    const float* Wv  = (const float*)d_in[6];
    const float* bv  = (const float*)d_in[7];
    const float* Wo  = (const float*)d_in[8];
    float* out = (float*)d_out;

    float *q, *k, *v, *cs, *sn;
    __half *xh, *xl, *qh, *ql, *kh, *kl, *vth, *vtl, *ath, *atl;
    __half *wqh, *wql, *wkh, *wkl, *wvh, *wvl, *woh, *wol;
    cudaGetSymbolAddress((void**)&q,   g_q);
    cudaGetSymbolAddress((void**)&k,   g_k);
    cudaGetSymbolAddress((void**)&v,   g_v);
    cudaGetSymbolAddress((void**)&cs,  g_cos);
    cudaGetSymbolAddress((void**)&sn,  g_sin);
    cudaGetSymbolAddress((void**)&xh,  g_xh);
    cudaGetSymbolAddress((void**)&xl,  g_xl);
    cudaGetSymbolAddress((void**)&qh,  g_qh);
    cudaGetSymbolAddress((void**)&ql,  g_ql);
    cudaGetSymbolAddress((void**)&kh,  g_kh);
    cudaGetSymbolAddress((void**)&kl,  g_kl);
    cudaGetSymbolAddress((void**)&vth, g_vth);
    cudaGetSymbolAddress((void**)&vtl, g_vtl);
    cudaGetSymbolAddress((void**)&ath, g_ath);
    cudaGetSymbolAddress((void**)&atl, g_atl);
    cudaGetSymbolAddress((void**)&wqh, g_wqh);
    cudaGetSymbolAddress((void**)&wql, g_wql);
    cudaGetSymbolAddress((void**)&wkh, g_wkh);
    cudaGetSymbolAddress((void**)&wkl, g_wkl);
    cudaGetSymbolAddress((void**)&wvh, g_wvh);
    cudaGetSymbolAddress((void**)&wvl, g_wvl);
    cudaGetSymbolAddress((void**)&woh, g_woh);
    cudaGetSymbolAddress((void**)&wol, g_wol);

    cudaFuncSetAttribute(tc_gemm, cudaFuncAttributeMaxDynamicSharedMemorySize, SM_GTOTAL);
    cudaFuncSetAttribute(attn_tc, cudaFuncAttributeMaxDynamicSharedMemorySize, AS_TOTAL);

    const float SCALE = 0.125f * 1.4426950408889634f;
    dim3 tb(32, 8);

    // 0) operand prep
    xsplit_kernel<<<(MQ * Hc / 4 + 255) / 256, 256>>>(x, xh, xl, MQ * Hc / 4);
    wconv_kernel<<<dim3(2048 / 32, 2048 / 32), tb>>>(Wq, wqh, wql, 2048, 2048);
    wconv_kernel<<<dim3(512  / 32, 2048 / 32), tb>>>(Wk, wkh, wkl, 2048, 512);
    wconv_kernel<<<dim3(512  / 32, 2048 / 32), tb>>>(Wv, wvh, wvl, 2048, 512);
    wconv_kernel<<<dim3(2048 / 32, 2048 / 32), tb>>>(Wo, woh, wol, 2048, 2048);
    cossin_kernel<<<(MQ * HDc + 255) / 256, 256>>>(pos, cs, sn);

    // 1) QKV projections (fp16x3 tcgen05)
    tc_gemm<<<dim3(16, 32), GEMM_THREADS, SM_GTOTAL>>>(xh, xl, wqh, wql, bq, q, 2048, Hc);
    tc_gemm<<<dim3(4,  32), GEMM_THREADS, SM_GTOTAL>>>(xh, xl, wkh, wkl, bk, k, 512,  Hc);
    tc_gemm<<<dim3(4,  32), GEMM_THREADS, SM_GTOTAL>>>(xh, xl, wvh, wvl, bv, v, 512,  Hc);

    // 2) RoPE + split; V transpose + split
    rope_split_kernel<<<(MQ * NHc * 32 + 255) / 256, 256>>>(q, cs, sn, qh, ql, NHc, SCALE, MQ * NHc * 32);
    rope_split_kernel<<<(MQ * NKVc * 32 + 255) / 256, 256>>>(k, cs, sn, kh, kl, NKVc, 1.0f, MQ * NKVc * 32);
    vtrans_kernel<<<dim3(Sc / 32, HDc / 32, Bc * NKVc), tb>>>(v, vth, vtl);

    // 3) tensor-core causal GQA attention -> pre-split att
    attn_tc<<<dim3(16, NHc, Bc), ATT_THREADS, AS_TOTAL>>>(qh, ql, kh, kl, vth, vtl, ath, atl);

    // 4) output projection
    tc_gemm<<<dim3(16, 32), GEMM_THREADS, SM_GTOTAL>>>(ath, atl, woh, wol, nullptr, out, 2048, Hc);
}